// round 12
// baseline (speedup 1.0000x reference)
#include <cuda_runtime.h>
#include <cuda_bf16.h>
#include <math.h>
#include <stdint.h>

#define BATCH   16
#define PSEQ    1024
#define NTOK    (BATCH*PSEQ)     // 16384
#define EMB     512
#define FFD     2048
#define NLAYER  4
#define NHEAD   8
#define DKH     64

typedef __nv_bfloat16 bf16;

// ---------------- scratch (static device globals; no runtime alloc) ----------
__device__ float g_x [NTOK*EMB];
__device__ float g_t [NTOK*EMB];
__device__ float g_pe[PSEQ*EMB];
__device__ bf16 g_xh[NTOK*EMB],  g_xl[NTOK*EMB];
__device__ bf16 g_qkvh[NTOK*3*EMB], g_qkvl[NTOK*3*EMB];
__device__ bf16 g_ah[NTOK*EMB],  g_al[NTOK*EMB];
__device__ bf16 g_hh[NTOK*FFD],  g_hl[NTOK*FFD];
__device__ bf16 g_wqkvh[NLAYER*3*EMB*EMB], g_wqkvl[NLAYER*3*EMB*EMB];
__device__ bf16 g_woh[NLAYER*EMB*EMB],     g_wol[NLAYER*EMB*EMB];
__device__ bf16 g_w1h[NLAYER*FFD*EMB],     g_w1l[NLAYER*FFD*EMB];
__device__ bf16 g_w2h[NLAYER*EMB*FFD],     g_w2l[NLAYER*EMB*FFD];
__device__ float g_bqkv[NLAYER*3*EMB];

// ============================================================================
// helpers
// ============================================================================
static __device__ __forceinline__ uint32_t smem_u32(const void* p) {
    uint32_t a;
    asm("{ .reg .u64 t; cvta.to.shared.u64 t, %1; cvt.u32.u64 %0, t; }"
        : "=r"(a) : "l"(p));
    return a;
}
static __device__ __forceinline__ uint32_t pack_hi(float a, float b, float& ra, float& rb) {
    bf16 ha = __float2bfloat16(a);
    bf16 hb = __float2bfloat16(b);
    ra = a - __bfloat162float(ha);
    rb = b - __bfloat162float(hb);
    return (uint32_t)__bfloat16_as_ushort(ha) | ((uint32_t)__bfloat16_as_ushort(hb) << 16);
}
static __device__ __forceinline__ uint32_t pack_lo(float a, float b) {
    return (uint32_t)__bfloat16_as_ushort(__float2bfloat16(a)) |
           ((uint32_t)__bfloat16_as_ushort(__float2bfloat16(b)) << 16);
}

#define MMA_BF16(d, a, b) \
    asm volatile("mma.sync.aligned.m16n8k16.row.col.f32.bf16.bf16.f32 " \
        "{%0,%1,%2,%3}, {%4,%5,%6,%7}, {%8,%9}, {%0,%1,%2,%3};" \
        : "+f"((d)[0]), "+f"((d)[1]), "+f"((d)[2]), "+f"((d)[3]) \
        : "r"((a)[0]), "r"((a)[1]), "r"((a)[2]), "r"((a)[3]), \
          "r"((b)[0]), "r"((b)[1]))

#define LDSM4(r, addr) \
    asm volatile("ldmatrix.sync.aligned.m8n8.x4.shared.b16 {%0,%1,%2,%3}, [%4];" \
        : "=r"((r)[0]), "=r"((r)[1]), "=r"((r)[2]), "=r"((r)[3]) : "r"(addr))

#define LDSM4T(r, addr) \
    asm volatile("ldmatrix.sync.aligned.m8n8.x4.trans.shared.b16 {%0,%1,%2,%3}, [%4];" \
        : "=r"((r)[0]), "=r"((r)[1]), "=r"((r)[2]), "=r"((r)[3]) : "r"(addr))

#define LDSM2(r, addr) \
    asm volatile("ldmatrix.sync.aligned.m8n8.x2.shared.b16 {%0,%1}, [%2];" \
        : "=r"((r)[0]), "=r"((r)[1]) : "r"(addr))

static __device__ __forceinline__ void cpa16(uint32_t d, const void* s) {
    asm volatile("cp.async.cg.shared.global [%0], [%1], 16;" :: "r"(d), "l"(s));
}

// swizzled byte offset inside a 128x32-bf16 tile (rows of 64B = 4x16B chunks)
static __device__ __forceinline__ uint32_t swz32(int r, int c) {
    return (uint32_t)(r * 64 + ((c ^ ((r >> 1) & 3)) << 4));
}

// ============================================================================
// bf16 HMMA GEMM on pre-split operands: C = (Ah+Al) @ (Wh+Wl)^T + bias
// (3-term: AhWh + AhWl + AlWh).  BM=BN=128, BK=32, 2-stage cp.async,
// 2 CTAs/SM. Term-major MMA order: 3 passes of 16 independent MMAs
// (RAW reuse distance 16; per-accumulator order unchanged -> bit-identical).
// ============================================================================
#define GSTAGE 32768u
#define GSMEM_BYTES (2*GSTAGE)   // 65536

template<int RELU, int SPLIT>
__global__ __launch_bounds__(256, 2)
void gemm_bf(const bf16* __restrict__ Ah, const bf16* __restrict__ Al,
             const bf16* __restrict__ Wh, const bf16* __restrict__ Wl,
             const float* __restrict__ bias,
             float* __restrict__ Cf, bf16* __restrict__ Ch, bf16* __restrict__ Cl,
             int M, int N, int K) {
    extern __shared__ __align__(16) char dsm[];
    const uint32_t sb = smem_u32(dsm);
    const int tid = threadIdx.x, lane = tid & 31, wid = tid >> 5;
    const int wm = wid & 3, wn = wid >> 2;
    const int bx = blockIdx.x, by = blockIdx.y;
    const int KT = K >> 5;

    float acc[2][8][4];
#pragma unroll
    for (int i = 0; i < 2; i++)
#pragma unroll
        for (int j = 0; j < 8; j++)
#pragma unroll
            for (int q = 0; q < 4; q++) acc[i][j][q] = 0.f;

    const int cr = tid >> 2, cc = tid & 3;
    const size_t aoff = (size_t)(by*128 + cr)*K + cc*8;
    const size_t woff = (size_t)(bx*128 + cr)*K + cc*8;
    const uint32_t so0 = swz32(cr, cc), so1 = swz32(cr + 64, cc);

    const int l16 = lane & 15;
    const int rB = (lane & 7) + ((lane >> 4) << 3);
    const int cB = (lane >> 3) & 1;

#define G_ISSUE(ktn) do {                                                     \
    if ((ktn) < KT) {                                                         \
        const uint32_t stb = sb + (uint32_t)((ktn) & 1) * GSTAGE;             \
        const int ko = (ktn) * 32;                                            \
        cpa16(stb + so0,           Ah + aoff + ko);                           \
        cpa16(stb + so1,           Ah + aoff + (size_t)64*K + ko);            \
        cpa16(stb + 8192u + so0,   Al + aoff + ko);                           \
        cpa16(stb + 8192u + so1,   Al + aoff + (size_t)64*K + ko);            \
        cpa16(stb + 16384u + so0,  Wh + woff + ko);                           \
        cpa16(stb + 16384u + so1,  Wh + woff + (size_t)64*K + ko);            \
        cpa16(stb + 24576u + so0,  Wl + woff + ko);                           \
        cpa16(stb + 24576u + so1,  Wl + woff + (size_t)64*K + ko);            \
    }                                                                         \
    asm volatile("cp.async.commit_group;" ::: "memory");                      \
} while (0)

    G_ISSUE(0);

    for (int kt = 0; kt < KT; kt++) {
        G_ISSUE(kt + 1);
        asm volatile("cp.async.wait_group 1;" ::: "memory");
        __syncthreads();

        const uint32_t stb = sb + (uint32_t)(kt & 1) * GSTAGE;
#pragma unroll
        for (int ks = 0; ks < 2; ks++) {
            uint32_t ah[2][4], al[2][4];
            uint32_t bh[4][4], bl[4][4];
#pragma unroll
            for (int mt = 0; mt < 2; mt++) {
                const uint32_t oa = stb + swz32(wm*32 + mt*16 + l16, ks*2 + (lane >> 4));
                LDSM4(ah[mt], oa);
                LDSM4(al[mt], oa + 8192u);
            }
#pragma unroll
            for (int ntp = 0; ntp < 4; ntp++) {
                const uint32_t ob = stb + 16384u + swz32(wn*64 + ntp*16 + rB, ks*2 + cB);
                LDSM4(bh[ntp], ob);
                LDSM4(bl[ntp], ob + 8192u);
            }
            // pass 1: ah x bh (16 independent MMAs)
#pragma unroll
            for (int ntp = 0; ntp < 4; ntp++)
#pragma unroll
                for (int mt = 0; mt < 2; mt++) {
                    MMA_BF16(acc[mt][2*ntp],   ah[mt], bh[ntp]);
                    MMA_BF16(acc[mt][2*ntp+1], ah[mt], &bh[ntp][2]);
                }
            // pass 2: ah x bl
#pragma unroll
            for (int ntp = 0; ntp < 4; ntp++)
#pragma unroll
                for (int mt = 0; mt < 2; mt++) {
                    MMA_BF16(acc[mt][2*ntp],   ah[mt], bl[ntp]);
                    MMA_BF16(acc[mt][2*ntp+1], ah[mt], &bl[ntp][2]);
                }
            // pass 3: al x bh
#pragma unroll
            for (int ntp = 0; ntp < 4; ntp++)
#pragma unroll
                for (int mt = 0; mt < 2; mt++) {
                    MMA_BF16(acc[mt][2*ntp],   al[mt], bh[ntp]);
                    MMA_BF16(acc[mt][2*ntp+1], al[mt], &bh[ntp][2]);
                }
        }
        __syncthreads();   // reads of buffer kt&1 done before it is re-filled
    }

    const int rbase = by*128 + wm*32 + (lane >> 2);
    const int cbase = bx*128 + wn*64 + 2*(lane & 3);
#pragma unroll
    for (int mt = 0; mt < 2; mt++) {
#pragma unroll
        for (int nt = 0; nt < 8; nt++) {
            const int row = rbase + mt*16;
            const int col = cbase + nt*8;
            const float b0 = bias[col], b1 = bias[col+1];
            float v0x = acc[mt][nt][0] + b0, v0y = acc[mt][nt][1] + b1;
            float v1x = acc[mt][nt][2] + b0, v1y = acc[mt][nt][3] + b1;
            if (RELU) {
                v0x = fmaxf(v0x, 0.f); v0y = fmaxf(v0y, 0.f);
                v1x = fmaxf(v1x, 0.f); v1y = fmaxf(v1y, 0.f);
            }
            if (SPLIT) {
                float rx, ry;
                uint32_t h = pack_hi(v0x, v0y, rx, ry);
                uint32_t l = pack_lo(rx, ry);
                *(uint32_t*)(Ch + (size_t)row*N + col) = h;
                *(uint32_t*)(Cl + (size_t)row*N + col) = l;
                h = pack_hi(v1x, v1y, rx, ry);
                l = pack_lo(rx, ry);
                *(uint32_t*)(Ch + (size_t)(row+8)*N + col) = h;
                *(uint32_t*)(Cl + (size_t)(row+8)*N + col) = l;
            } else {
                float2 a = {v0x, v0y}, b = {v1x, v1y};
                *(float2*)(Cf + (size_t)row*N + col)     = a;
                *(float2*)(Cf + (size_t)(row+8)*N + col) = b;
            }
        }
    }
}

// ============================================================================
// HMMA flash attention, Q-tile 128, cp.async double-buffered K/V.
// grid (P/128, NH, B), 256 threads = 8 warps (16 q-rows each).
// Pairwise-interleaved MMA issue (per-acc order unchanged -> bit-identical).
// ============================================================================
#define AST 72
#define KVSTG 36864u
#define ATT_SMEM_BYTES (36864 + 2*36864)   // 110592

__global__ __launch_bounds__(256)
void attn_mma(const bf16* __restrict__ QKVh, const bf16* __restrict__ QKVl,
              bf16* __restrict__ Ah, bf16* __restrict__ Al) {
    extern __shared__ __align__(16) char smx[];
    const uint32_t sb = smem_u32(smx);

    const int tid = threadIdx.x;
    const int lane = tid & 31;
    const int wid = tid >> 5;          // 0..7
    const int l16 = lane & 15;
    const int qt = blockIdx.x, hh = blockIdx.y, bb = blockIdx.z;
    const int nbase = bb * PSEQ;
    const int hoff  = hh * DKH;

#define KV_ISSUE(kcn) do {                                                    \
    if ((kcn) < 16) {                                                         \
        const uint32_t B = sb + 36864u + (uint32_t)((kcn) & 1) * KVSTG;       \
        _Pragma("unroll")                                                     \
        for (int it = 0; it < 2; it++) {                                      \
            int idx = tid + it*256;                                           \
            int r = idx >> 3;                                                 \
            int c8 = (idx & 7) * 8;                                           \
            const size_t go = (size_t)(nbase + (kcn)*64 + r)*(3*EMB) + hoff + c8; \
            const uint32_t o = (uint32_t)(r*144 + c8*2);                      \
            cpa16(B + o,           QKVh + 512 + go);                          \
            cpa16(B + 9216u + o,   QKVl + 512 + go);                          \
            cpa16(B + 18432u + o,  QKVh + 1024 + go);                         \
            cpa16(B + 27648u + o,  QKVl + 1024 + go);                         \
        }                                                                     \
    }                                                                         \
    asm volatile("cp.async.commit_group;" ::: "memory");                      \
} while (0)

    // ---- Q tile (128x64) via cp.async; grouped with KV chunk 0 ----
#pragma unroll
    for (int it = 0; it < 4; it++) {
        int idx = tid + it*256;
        int r = idx >> 3;
        int c8 = (idx & 7) * 8;
        const size_t go = (size_t)(nbase + qt*128 + r)*(3*EMB) + hoff + c8;
        const uint32_t o = (uint32_t)(r*144 + c8*2);
        cpa16(sb + o,           QKVh + go);
        cpa16(sb + 18432u + o,  QKVl + go);
    }
    KV_ISSUE(0);      // group0 = {Q, KV0}
    KV_ISSUE(1);      // group1 = {KV1}

    float o_acc[8][4];
#pragma unroll
    for (int i = 0; i < 8; i++)
#pragma unroll
        for (int j = 0; j < 4; j++) o_acc[i][j] = 0.f;
    float m_g = -1e30f, m_g8 = -1e30f, l_g = 0.f, l_g8 = 0.f;

    uint32_t qh[4][4], ql[4][4];
    const uint32_t offA = (uint32_t)(((wid*16 + l16) * AST + (lane >> 4) * 8) * 2);
    const uint32_t offBr = (uint32_t)((((l16 & 7)) * AST + ((l16 >> 3)) * 8) * 2);
    const uint32_t offVt = (uint32_t)((((lane & 7) + ((lane >> 3) & 1) * 8)) * AST * 2
                                      + ((lane >> 4) * 8) * 2);

    for (int kc = 0; kc < 16; kc++) {
        asm volatile("cp.async.wait_group 1;" ::: "memory");
        __syncthreads();
        const uint32_t stB = sb + 36864u + (uint32_t)(kc & 1) * KVSTG;

        if (kc == 0) {
#pragma unroll
            for (int ks = 0; ks < 4; ks++) {
                LDSM4(qh[ks], sb + offA + (uint32_t)(ks*32));
                LDSM4(ql[ks], sb + 18432u + offA + (uint32_t)(ks*32));
            }
        }

        // ---- S = Q @ K^T : process nt in pairs, interleave accumulators ----
        float s[8][4];
#pragma unroll
        for (int nt = 0; nt < 8; nt++)
#pragma unroll
            for (int j = 0; j < 4; j++) s[nt][j] = 0.f;
#pragma unroll
        for (int np = 0; np < 4; np++) {
            const int n0 = 2*np, n1 = 2*np + 1;
#pragma unroll
            for (int ks = 0; ks < 4; ks++) {
                uint32_t bh0[2], bl0[2], bh1[2], bl1[2];
                const uint32_t bo0 = offBr + (uint32_t)(n0*8*AST*2 + ks*32);
                const uint32_t bo1 = offBr + (uint32_t)(n1*8*AST*2 + ks*32);
                LDSM2(bh0, stB + bo0);
                LDSM2(bl0, stB + 9216u + bo0);
                LDSM2(bh1, stB + bo1);
                LDSM2(bl1, stB + 9216u + bo1);
                MMA_BF16(s[n0], qh[ks], bh0);
                MMA_BF16(s[n1], qh[ks], bh1);
                MMA_BF16(s[n0], ql[ks], bh0);
                MMA_BF16(s[n1], ql[ks], bh1);
                MMA_BF16(s[n0], qh[ks], bl0);
                MMA_BF16(s[n1], qh[ks], bl1);
            }
        }
#pragma unroll
        for (int nt = 0; nt < 8; nt++) {
            s[nt][0] *= 0.125f; s[nt][1] *= 0.125f;
            s[nt][2] *= 0.125f; s[nt][3] *= 0.125f;
        }

        // ---- online softmax ----
        float cmg = -1e30f, cmg8 = -1e30f;
#pragma unroll
        for (int nt = 0; nt < 8; nt++) {
            cmg  = fmaxf(cmg,  fmaxf(s[nt][0], s[nt][1]));
            cmg8 = fmaxf(cmg8, fmaxf(s[nt][2], s[nt][3]));
        }
        cmg  = fmaxf(cmg,  __shfl_xor_sync(0xffffffffu, cmg, 1));
        cmg  = fmaxf(cmg,  __shfl_xor_sync(0xffffffffu, cmg, 2));
        cmg8 = fmaxf(cmg8, __shfl_xor_sync(0xffffffffu, cmg8, 1));
        cmg8 = fmaxf(cmg8, __shfl_xor_sync(0xffffffffu, cmg8, 2));
        const float mn  = fmaxf(m_g,  cmg);
        const float mn8 = fmaxf(m_g8, cmg8);
        const float alg  = __expf(m_g  - mn);
        const float alg8 = __expf(m_g8 - mn8);
        m_g = mn; m_g8 = mn8;
        float sum = 0.f, sum8 = 0.f;
#pragma unroll
        for (int nt = 0; nt < 8; nt++) {
            s[nt][0] = __expf(s[nt][0] - mn);
            s[nt][1] = __expf(s[nt][1] - mn);
            s[nt][2] = __expf(s[nt][2] - mn8);
            s[nt][3] = __expf(s[nt][3] - mn8);
            sum  += s[nt][0] + s[nt][1];
            sum8 += s[nt][2] + s[nt][3];
        }
        sum  += __shfl_xor_sync(0xffffffffu, sum, 1);
        sum  += __shfl_xor_sync(0xffffffffu, sum, 2);
        sum8 += __shfl_xor_sync(0xffffffffu, sum8, 1);
        sum8 += __shfl_xor_sync(0xffffffffu, sum8, 2);
        l_g  = l_g  * alg  + sum;
        l_g8 = l_g8 * alg8 + sum8;
#pragma unroll
        for (int dt = 0; dt < 8; dt++) {
            o_acc[dt][0] *= alg;  o_acc[dt][1] *= alg;
            o_acc[dt][2] *= alg8; o_acc[dt][3] *= alg8;
        }

        // ---- P fragments from S accums ----
        uint32_t ph[4][4], pl[4][4];
#pragma unroll
        for (int ks = 0; ks < 4; ks++) {
            float r0, r1;
            ph[ks][0] = pack_hi(s[2*ks][0],   s[2*ks][1],   r0, r1); pl[ks][0] = pack_lo(r0, r1);
            ph[ks][1] = pack_hi(s[2*ks][2],   s[2*ks][3],   r0, r1); pl[ks][1] = pack_lo(r0, r1);
            ph[ks][2] = pack_hi(s[2*ks+1][0], s[2*ks+1][1], r0, r1); pl[ks][2] = pack_lo(r0, r1);
            ph[ks][3] = pack_hi(s[2*ks+1][2], s[2*ks+1][3], r0, r1); pl[ks][3] = pack_lo(r0, r1);
        }

        // ---- O += P @ V (trans ldmatrix; term-major across acc pair) ----
#pragma unroll
        for (int dt2 = 0; dt2 < 4; dt2++) {
#pragma unroll
            for (int ks = 0; ks < 4; ks++) {
                const uint32_t va = stB + 18432u + offVt
                    + (uint32_t)(ks*16*AST*2 + dt2*32);
                uint32_t vh4[4], vl4[4];
                LDSM4T(vh4, va);
                LDSM4T(vl4, va + 9216u);
                MMA_BF16(o_acc[2*dt2],   ph[ks], vh4);
                MMA_BF16(o_acc[2*dt2+1], ph[ks], &vh4[2]);
                MMA_BF16(o_acc[2*dt2],   pl[ks], vh4);
                MMA_BF16(o_acc[2*dt2+1], pl[ks], &vh4[2]);
                MMA_BF16(o_acc[2*dt2],   ph[ks], vl4);
                MMA_BF16(o_acc[2*dt2+1], ph[ks], &vl4[2]);
            }
        }
        __syncthreads();   // all reads of stage kc&1 done before refill
        KV_ISSUE(kc + 2);
    }

    // ---- epilogue: split-write a ----
    const float ig  = 1.f / l_g;
    const float ig8 = 1.f / l_g8;
    const int g = lane >> 2;
    const int r0 = nbase + qt*128 + wid*16 + g;
    const int cb = hoff + 2*(lane & 3);
#pragma unroll
    for (int dt = 0; dt < 8; dt++) {
        float v0x = o_acc[dt][0]*ig,  v0y = o_acc[dt][1]*ig;
        float v1x = o_acc[dt][2]*ig8, v1y = o_acc[dt][3]*ig8;
        float rx, ry;
        uint32_t h = pack_hi(v0x, v0y, rx, ry);
        uint32_t l = pack_lo(rx, ry);
        *(uint32_t*)(Ah + (size_t)r0*EMB + cb + dt*8) = h;
        *(uint32_t*)(Al + (size_t)r0*EMB + cb + dt*8) = l;
        h = pack_hi(v1x, v1y, rx, ry);
        l = pack_lo(rx, ry);
        *(uint32_t*)(Ah + (size_t)(r0+8)*EMB + cb + dt*8) = h;
        *(uint32_t*)(Al + (size_t)(r0+8)*EMB + cb + dt*8) = l;
    }
}

// ---------------- weight split / pack kernels --------------------------------
__global__ void split_w4(const float* __restrict__ src, bf16* __restrict__ h,
                         bf16* __restrict__ l, int n_per_layer, int dst_stride,
                         int dst_off) {
    int idx = blockIdx.x * blockDim.x + threadIdx.x;
    int total4 = (NLAYER * n_per_layer) >> 2;
    if (idx >= total4) return;
    int base = idx * 4;
    int layer = base / n_per_layer;
    int i = base - layer * n_per_layer;
    float4 v = *(const float4*)(src + base);
    float rx, ry;
    uint32_t h01 = pack_hi(v.x, v.y, rx, ry);
    uint32_t l01 = pack_lo(rx, ry);
    uint32_t h23 = pack_hi(v.z, v.w, rx, ry);
    uint32_t l23 = pack_lo(rx, ry);
    size_t d = (size_t)layer * dst_stride + dst_off + i;
    uint2 hv = {h01, h23}, lv = {l01, l23};
    *(uint2*)(h + d) = hv;
    *(uint2*)(l + d) = lv;
}

__global__ void pack_bqkv(const float* __restrict__ bq, const float* __restrict__ bk,
                          const float* __restrict__ bv, float* __restrict__ dst) {
    int idx = blockIdx.x * blockDim.x + threadIdx.x;
    if (idx >= NLAYER * 3 * EMB) return;
    int l = idx / (3*EMB);
    int n = idx - l * 3*EMB;
    float v;
    if (n < EMB)            v = bq[l*EMB + n];
    else if (n < 2*EMB)     v = bk[l*EMB + n - EMB];
    else                    v = bv[l*EMB + n - 2*EMB];
    dst[idx] = v;
}

// ---------------- positional encoding table --------------------------------
__global__ void pe_kernel(float* __restrict__ pe) {
    int idx = blockIdx.x * blockDim.x + threadIdx.x;
    if (idx >= PSEQ*EMB) return;
    int p = idx >> 9;
    int e = idx & 511;
    int i2 = e >> 1;
    float c = (float)(2*i2) * (-0.017988946039015984f);
    float freqf = (float)exp((double)c);
    float angf  = (float)p * freqf;
    double angle = (double)angf;
    pe[idx] = (e & 1) ? (float)cos(angle) : (float)sin(angle);
}

// ---------------- embedding: conv + linear + PE, writes x + split ------------
__global__ void embed_kernel(const float* __restrict__ data,
                             const float* __restrict__ cw,
                             const float* __restrict__ cb,
                             const float* __restrict__ lw,
                             const float* __restrict__ lb,
                             const float* __restrict__ pe,
                             float* __restrict__ x,
                             bf16* __restrict__ xh, bf16* __restrict__ xl) {
    int idx = blockIdx.x * blockDim.x + threadIdx.x;
    if (idx >= NTOK*EMB) return;
    int n = idx >> 9;
    int e = idx & 511;
    int b = n >> 10;
    int p = n & 1023;
    int pi = p >> 5, pj = p & 31;
    const float* dp = data + b*4096 + (pi*2)*64 + pj*2;
    float conv = dp[0]*cw[0] + dp[1]*cw[1] + dp[64]*cw[2] + dp[65]*cw[3] + cb[0];
    float v = conv * lw[e] + lb[e] + pe[p*EMB + e];
    x[idx] = v;
    bf16 h = __float2bfloat16(v);
    xh[idx] = h;
    xl[idx] = __float2bfloat16(v - __bfloat162float(h));
}

// ---------------- residual add + LayerNorm, writes x + split -----------------
__global__ __launch_bounds__(128)
void add_ln_kernel(float* __restrict__ x, const float* __restrict__ y,
                   const float* __restrict__ gam, const float* __restrict__ bet,
                   bf16* __restrict__ xh, bf16* __restrict__ xl) {
    const int row = blockIdx.x;
    const int tid = threadIdx.x;
    const int e = tid * 4;
    float4 xv = *(float4*)&x[(size_t)row*EMB + e];
    float4 yv = *(const float4*)&y[(size_t)row*EMB + e];
    float t0 = xv.x + yv.x, t1 = xv.y + yv.y, t2 = xv.z + yv.z, t3 = xv.w + yv.w;
    float s  = t0 + t1 + t2 + t3;
    float s2 = t0*t0 + t1*t1 + t2*t2 + t3*t3;
#pragma unroll
    for (int off = 16; off > 0; off >>= 1) {
        s  += __shfl_xor_sync(0xffffffffu, s,  off);
        s2 += __shfl_xor_sync(0xffffffffu, s2, off);
    }
    __shared__ float ws[4], ws2[4];
    int w = tid >> 5;
    if ((tid & 31) == 0) { ws[w] = s; ws2[w] = s2; }
    __syncthreads();
    float S  = ws[0] + ws[1] + ws[2] + ws[3];
    float S2 = ws2[0] + ws2[1] + ws2[2] + ws2[3];
    float mu  = S * (1.f/512.f);
    float var = S2 * (1.f/512.f) - mu*mu;
    float rs = rsqrtf(var + 1e-5f);
    float o0 = (t0 - mu)*rs*gam[e+0] + bet[e+0];
    float o1 = (t1 - mu)*rs*gam[e+1] + bet[e+1];
    float o2 = (t2 - mu)*rs*gam[e+2] + bet[e+2];
    float o3 = (t3 - mu)*rs*gam[e+3] + bet[e+3];
    float4 ov = {o0, o1, o2, o3};
    *(float4*)&x[(size_t)row*EMB + e] = ov;
    float rx, ry;
    uint32_t h01 = pack_hi(o0, o1, rx, ry);
    uint32_t l01 = pack_lo(rx, ry);
    uint32_t h23 = pack_hi(o2, o3, rx, ry);
    uint32_t l23 = pack_lo(rx, ry);
    uint2 hv = {h01, h23}, lv = {l01, l23};
    *(uint2*)(xh + (size_t)row*EMB + e) = hv;
    *(uint2*)(xl + (size_t)row*EMB + e) = lv;
}

// ---------------- mean pool + final linear ----------------------------------
__global__ __launch_bounds__(512)
void pool_head_kernel(const float* __restrict__ x, const float* __restrict__ Wc,
                      const float* __restrict__ bc, float* __restrict__ out) {
    const int b = blockIdx.x;
    const int e = threadIdx.x;
    float s = 0.f;
    const float* xp = x + (size_t)b*PSEQ*EMB + e;
    for (int p = 0; p < PSEQ; p++) s += xp[(size_t)p*EMB];
    float pooled = s * (1.f/1024.f);
    __shared__ float red[512];
    red[e] = pooled * Wc[e];
    __syncthreads();
    for (int st = 256; st > 0; st >>= 1) {
        if (e < st) red[e] += red[e + st];
        __syncthreads();
    }
    if (e == 0) out[b] = red[0] + bc[0];
}

// ---------------- driver -----------------------------------------------------
extern "C" void kernel_launch(void* const* d_in, const int* in_sizes, int n_in,
                              void* d_out, int out_size) {
    const float* data   = (const float*)d_in[0];
    const float* conv_w = (const float*)d_in[1];
    const float* conv_b = (const float*)d_in[2];
    const float* lin_w  = (const float*)d_in[3];
    const float* lin_b  = (const float*)d_in[4];
    const float* Wq     = (const float*)d_in[5];
    const float* bq     = (const float*)d_in[6];
    const float* Wk     = (const float*)d_in[7];
    const float* bk     = (const float*)d_in[8];
    const float* Wv     = (const float*)d_in[9];
    const float* bv     = (const float*)d_in[10];
    const float* Wo     = (const float*)d_in[11];
    const float* bo     = (const float*)d_in[12];
    const float* ln1_g  = (const float*)d_in[13];
    const float* ln1_b  = (const float*)d_in[14];
    const float* ln2_g  = (const float*)d_in[15];
    const float* ln2_b  = (const float*)d_in[16];
    const float* W1     = (const float*)d_in[17];
    const float* b1     = (const float*)d_in[18];
    const float* W2     = (const float*)d_in[19];
    const float* b2     = (const float*)d_in[20];
    const float* Wc     = (const float*)d_in[21];
    const float* bc     = (const float*)d_in[22];
    float* out = (float*)d_out;

    float *px, *pt, *ppe, *pbqkv;
    bf16 *pxh, *pxl, *pqkvh, *pqkvl, *pah, *pal, *phh, *phl;
    bf16 *pwqkvh, *pwqkvl, *pwoh, *pwol, *pw1h, *pw1l, *pw2h, *pw2l;
    cudaGetSymbolAddress((void**)&px,  g_x);
    cudaGetSymbolAddress((void**)&pt,  g_t);
    cudaGetSymbolAddress((void**)&ppe, g_pe);
    cudaGetSymbolAddress((void**)&pxh, g_xh);
    cudaGetSymbolAddress((void**)&pxl, g_xl);
    cudaGetSymbolAddress((void**)&pqkvh, g_qkvh);
    cudaGetSymbolAddress((void**)&pqkvl, g_qkvl);
    cudaGetSymbolAddress((void**)&pah, g_ah);
    cudaGetSymbolAddress((void**)&pal, g_al);
    cudaGetSymbolAddress((void**)&phh, g_hh);
    cudaGetSymbolAddress((void**)&phl, g_hl);
    cudaGetSymbolAddress((void**)&pwqkvh, g_wqkvh);
    cudaGetSymbolAddress((void**)&pwqkvl, g_wqkvl);
    cudaGetSymbolAddress((void**)&pwoh, g_woh);
    cudaGetSymbolAddress((void**)&pwol, g_wol);
    cudaGetSymbolAddress((void**)&pw1h, g_w1h);
    cudaGetSymbolAddress((void**)&pw1l, g_w1l);
    cudaGetSymbolAddress((void**)&pw2h, g_w2h);
    cudaGetSymbolAddress((void**)&pw2l, g_w2l);
    cudaGetSymbolAddress((void**)&pbqkv, g_bqkv);

    cudaFuncSetAttribute(gemm_bf<0,0>, cudaFuncAttributeMaxDynamicSharedMemorySize, GSMEM_BYTES);
    cudaFuncSetAttribute(gemm_bf<0,1>, cudaFuncAttributeMaxDynamicSharedMemorySize, GSMEM_BYTES);
    cudaFuncSetAttribute(gemm_bf<1,1>, cudaFuncAttributeMaxDynamicSharedMemorySize, GSMEM_BYTES);
    cudaFuncSetAttribute(attn_mma, cudaFuncAttributeMaxDynamicSharedMemorySize, ATT_SMEM_BYTES);

    // ---- weight/bias packing (once per call) ----
    const int EE = EMB*EMB;          // 262144
    const int FE = FFD*EMB;          // 1048576
    split_w4<<<(NLAYER*EE/4 + 255)/256, 256>>>(Wq, pwqkvh, pwqkvl, EE, 3*EE, 0);
    split_w4<<<(NLAYER*EE/4 + 255)/256, 256>>>(Wk, pwqkvh, pwqkvl, EE, 3*EE, EE);
    split_w4<<<(NLAYER*EE/4 + 255)/256, 256>>>(Wv, pwqkvh, pwqkvl, EE, 3*EE, 2*EE);
    split_w4<<<(NLAYER*EE/4 + 255)/256, 256>>>(Wo, pwoh, pwol, EE, EE, 0);
    split_w4<<<(NLAYER*FE/4 + 255)/256, 256>>>(W1, pw1h, pw1l, FE, FE, 0);
    split_w4<<<(NLAYER*FE/4 + 255)/256, 256>>>(W2, pw2h, pw2l, FE, FE, 0);
    pack_bqkv<<<(NLAYER*3*EMB + 255)/256, 256>>>(bq, bk, bv, pbqkv);

    pe_kernel<<<(PSEQ*EMB + 255)/256, 256>>>(ppe);
    embed_kernel<<<(NTOK*EMB + 255)/256, 256>>>(data, conv_w, conv_b, lin_w, lin_b,
                                                ppe, px, pxh, pxl);

    for (int l = 0; l < NLAYER; l++) {
        // fused QKV: [NTOK,512] @ [1536,512]^T -> split qkv
        gemm_bf<0,1><<<dim3(12,128), 256, GSMEM_BYTES>>>(
            pxh, pxl, pwqkvh + (size_t)l*3*EE, pwqkvl + (size_t)l*3*EE,
            pbqkv + l*3*EMB, nullptr, pqkvh, pqkvl, NTOK, 3*EMB, EMB);

        attn_mma<<<dim3(PSEQ/128, NHEAD, BATCH), 256, ATT_SMEM_BYTES>>>(
            pqkvh, pqkvl, pah, pal);

        gemm_bf<0,0><<<dim3(4,128), 256, GSMEM_BYTES>>>(
            pah, pal, pwoh + (size_t)l*EE, pwol + (size_t)l*EE,
            bo + l*EMB, pt, nullptr, nullptr, NTOK, EMB, EMB);
        add_ln_kernel<<<NTOK, 128>>>(px, pt, ln1_g + l*EMB, ln1_b + l*EMB, pxh, pxl);

        gemm_bf<1,1><<<dim3(16,128), 256, GSMEM_BYTES>>>(
            pxh, pxl, pw1h + (size_t)l*FE, pw1l + (size_t)l*FE,
            b1 + l*FFD, nullptr, phh, phl, NTOK, FFD, EMB);

        gemm_bf<0,0><<<dim3(4,128), 256, GSMEM_BYTES>>>(
            phh, phl, pw2h + (size_t)l*FE, pw2l + (size_t)l*FE,
            b2 + l*EMB, pt, nullptr, nullptr, NTOK, EMB, FFD);
        add_ln_kernel<<<NTOK, 128>>>(px, pt, ln2_g + l*EMB, ln2_b + l*EMB, pxh, pxl);
    }

    pool_head_kernel<<<BATCH, 512>>>(px, Wc, bc, out);
}

// round 13
// speedup vs baseline: 1.2664x; 1.2664x over previous
#include <cuda_runtime.h>
#include <cuda_fp16.h>
#include <math.h>
#include <stdint.h>

#define BATCH   16
#define PSEQ    1024
#define NTOK    (BATCH*PSEQ)     // 16384
#define EMB     512
#define FFD     2048
#define NLAYER  4
#define NHEAD   8
#define DKH     64

typedef __half hf;

// ---------------- scratch (static device globals; no runtime alloc) ----------
__device__ float g_x [NTOK*EMB];
__device__ float g_t [NTOK*EMB];
__device__ float g_pe[PSEQ*EMB];
__device__ hf g_xh[NTOK*EMB];                       // single fp16 activations
__device__ hf g_qkvh[NTOK*3*EMB], g_qkvl[NTOK*3*EMB];
__device__ hf g_ah[NTOK*EMB];
__device__ hf g_hh[NTOK*FFD];
__device__ hf g_wqkvh[NLAYER*3*EMB*EMB], g_wqkvl[NLAYER*3*EMB*EMB];
__device__ hf g_woh[NLAYER*EMB*EMB],     g_wol[NLAYER*EMB*EMB];
__device__ hf g_w1h[NLAYER*FFD*EMB],     g_w1l[NLAYER*FFD*EMB];
__device__ hf g_w2h[NLAYER*EMB*FFD],     g_w2l[NLAYER*EMB*FFD];
__device__ float g_bqkv[NLAYER*3*EMB];

// ============================================================================
// helpers
// ============================================================================
static __device__ __forceinline__ uint32_t smem_u32(const void* p) {
    uint32_t a;
    asm("{ .reg .u64 t; cvta.to.shared.u64 t, %1; cvt.u32.u64 %0, t; }"
        : "=r"(a) : "l"(p));
    return a;
}
static __device__ __forceinline__ uint32_t pack2(float a, float b) {
    __half2 t = __floats2half2_rn(a, b);
    return *reinterpret_cast<uint32_t*>(&t);
}
static __device__ __forceinline__ uint32_t pack_hi2(float a, float b, float& ra, float& rb) {
    hf ha = __float2half_rn(a);
    hf hb = __float2half_rn(b);
    ra = a - __half2float(ha);
    rb = b - __half2float(hb);
    return (uint32_t)__half_as_ushort(ha) | ((uint32_t)__half_as_ushort(hb) << 16);
}

#define MMA_F16(d, a, b) \
    asm volatile("mma.sync.aligned.m16n8k16.row.col.f32.f16.f16.f32 " \
        "{%0,%1,%2,%3}, {%4,%5,%6,%7}, {%8,%9}, {%0,%1,%2,%3};" \
        : "+f"((d)[0]), "+f"((d)[1]), "+f"((d)[2]), "+f"((d)[3]) \
        : "r"((a)[0]), "r"((a)[1]), "r"((a)[2]), "r"((a)[3]), \
          "r"((b)[0]), "r"((b)[1]))

#define LDSM4(r, addr) \
    asm volatile("ldmatrix.sync.aligned.m8n8.x4.shared.b16 {%0,%1,%2,%3}, [%4];" \
        : "=r"((r)[0]), "=r"((r)[1]), "=r"((r)[2]), "=r"((r)[3]) : "r"(addr))

#define LDSM4T(r, addr) \
    asm volatile("ldmatrix.sync.aligned.m8n8.x4.trans.shared.b16 {%0,%1,%2,%3}, [%4];" \
        : "=r"((r)[0]), "=r"((r)[1]), "=r"((r)[2]), "=r"((r)[3]) : "r"(addr))

#define LDSM2(r, addr) \
    asm volatile("ldmatrix.sync.aligned.m8n8.x2.shared.b16 {%0,%1}, [%2];" \
        : "=r"((r)[0]), "=r"((r)[1]) : "r"(addr))

static __device__ __forceinline__ void cpa16(uint32_t d, const void* s) {
    asm volatile("cp.async.cg.shared.global [%0], [%1], 16;" :: "r"(d), "l"(s));
}

// swizzled byte offset inside a 128x32-hf tile (rows of 64B = 4x16B chunks)
static __device__ __forceinline__ uint32_t swz32(int r, int c) {
    return (uint32_t)(r * 64 + ((c ^ ((r >> 1) & 3)) << 4));
}

// ============================================================================
// fp16 HMMA GEMM: C = A @ (Wh+Wl)^T + bias   (2 terms: A*Wh + A*Wl)
// A single fp16; W split hi/lo fp16. BM=BN=128, BK=32, 2-stage cp.async,
// 2 CTAs/SM. 256 threads = 4(M) x 2(N) warps; warp tile 32x64.
// OUT: 0 = fp32, 1 = split fp16 hi/lo, 2 = single fp16.
// ============================================================================
#define GSTAGE 24576u
#define GSMEM_BYTES (2*GSTAGE)   // 49152

template<int RELU, int OUT>
__global__ __launch_bounds__(256, 2)
void gemm_hf(const hf* __restrict__ A,
             const hf* __restrict__ Wh, const hf* __restrict__ Wl,
             const float* __restrict__ bias,
             float* __restrict__ Cf, hf* __restrict__ Ch, hf* __restrict__ Cl,
             int M, int N, int K) {
    extern __shared__ __align__(16) char dsm[];
    const uint32_t sb = smem_u32(dsm);
    const int tid = threadIdx.x, lane = tid & 31, wid = tid >> 5;
    const int wm = wid & 3, wn = wid >> 2;
    const int bx = blockIdx.x, by = blockIdx.y;
    const int KT = K >> 5;

    float acc[2][8][4];
#pragma unroll
    for (int i = 0; i < 2; i++)
#pragma unroll
        for (int j = 0; j < 8; j++)
#pragma unroll
            for (int q = 0; q < 4; q++) acc[i][j][q] = 0.f;

    const int cr = tid >> 2, cc = tid & 3;
    const size_t aoff = (size_t)(by*128 + cr)*K + cc*8;
    const size_t woff = (size_t)(bx*128 + cr)*K + cc*8;
    const uint32_t so0 = swz32(cr, cc), so1 = swz32(cr + 64, cc);

    const int l16 = lane & 15;
    const int rB = (lane & 7) + ((lane >> 4) << 3);
    const int cB = (lane >> 3) & 1;

#define G_ISSUE(ktn) do {                                                     \
    if ((ktn) < KT) {                                                         \
        const uint32_t stb = sb + (uint32_t)((ktn) & 1) * GSTAGE;             \
        const int ko = (ktn) * 32;                                            \
        cpa16(stb + so0,           A  + aoff + ko);                           \
        cpa16(stb + so1,           A  + aoff + (size_t)64*K + ko);            \
        cpa16(stb + 8192u + so0,   Wh + woff + ko);                           \
        cpa16(stb + 8192u + so1,   Wh + woff + (size_t)64*K + ko);            \
        cpa16(stb + 16384u + so0,  Wl + woff + ko);                           \
        cpa16(stb + 16384u + so1,  Wl + woff + (size_t)64*K + ko);            \
    }                                                                         \
    asm volatile("cp.async.commit_group;" ::: "memory");                      \
} while (0)

    G_ISSUE(0);

    for (int kt = 0; kt < KT; kt++) {
        G_ISSUE(kt + 1);
        asm volatile("cp.async.wait_group 1;" ::: "memory");
        __syncthreads();

        const uint32_t stb = sb + (uint32_t)(kt & 1) * GSTAGE;
#pragma unroll
        for (int ks = 0; ks < 2; ks++) {
            uint32_t ah[2][4];
            uint32_t bh[4][4], bl[4][4];
#pragma unroll
            for (int mt = 0; mt < 2; mt++) {
                const uint32_t oa = stb + swz32(wm*32 + mt*16 + l16, ks*2 + (lane >> 4));
                LDSM4(ah[mt], oa);
            }
#pragma unroll
            for (int ntp = 0; ntp < 4; ntp++) {
                const uint32_t ob = stb + 8192u + swz32(wn*64 + ntp*16 + rB, ks*2 + cB);
                LDSM4(bh[ntp], ob);
                LDSM4(bl[ntp], ob + 8192u);
            }
            // pass 1: a x Wh
#pragma unroll
            for (int ntp = 0; ntp < 4; ntp++)
#pragma unroll
                for (int mt = 0; mt < 2; mt++) {
                    MMA_F16(acc[mt][2*ntp],   ah[mt], bh[ntp]);
                    MMA_F16(acc[mt][2*ntp+1], ah[mt], &bh[ntp][2]);
                }
            // pass 2: a x Wl
#pragma unroll
            for (int ntp = 0; ntp < 4; ntp++)
#pragma unroll
                for (int mt = 0; mt < 2; mt++) {
                    MMA_F16(acc[mt][2*ntp],   ah[mt], bl[ntp]);
                    MMA_F16(acc[mt][2*ntp+1], ah[mt], &bl[ntp][2]);
                }
        }
        __syncthreads();   // reads of buffer kt&1 done before it is re-filled
    }

    const int rbase = by*128 + wm*32 + (lane >> 2);
    const int cbase = bx*128 + wn*64 + 2*(lane & 3);
#pragma unroll
    for (int mt = 0; mt < 2; mt++) {
#pragma unroll
        for (int nt = 0; nt < 8; nt++) {
            const int row = rbase + mt*16;
            const int col = cbase + nt*8;
            const float b0 = bias[col], b1 = bias[col+1];
            float v0x = acc[mt][nt][0] + b0, v0y = acc[mt][nt][1] + b1;
            float v1x = acc[mt][nt][2] + b0, v1y = acc[mt][nt][3] + b1;
            if (RELU) {
                v0x = fmaxf(v0x, 0.f); v0y = fmaxf(v0y, 0.f);
                v1x = fmaxf(v1x, 0.f); v1y = fmaxf(v1y, 0.f);
            }
            if (OUT == 1) {
                float rx, ry;
                uint32_t h = pack_hi2(v0x, v0y, rx, ry);
                uint32_t l = pack2(rx, ry);
                *(uint32_t*)(Ch + (size_t)row*N + col) = h;
                *(uint32_t*)(Cl + (size_t)row*N + col) = l;
                h = pack_hi2(v1x, v1y, rx, ry);
                l = pack2(rx, ry);
                *(uint32_t*)(Ch + (size_t)(row+8)*N + col) = h;
                *(uint32_t*)(Cl + (size_t)(row+8)*N + col) = l;
            } else if (OUT == 2) {
                *(uint32_t*)(Ch + (size_t)row*N + col)     = pack2(v0x, v0y);
                *(uint32_t*)(Ch + (size_t)(row+8)*N + col) = pack2(v1x, v1y);
            } else {
                float2 a = {v0x, v0y}, b = {v1x, v1y};
                *(float2*)(Cf + (size_t)row*N + col)     = a;
                *(float2*)(Cf + (size_t)(row+8)*N + col) = b;
            }
        }
    }
}

// ============================================================================
// fp16 HMMA flash attention, Q-tile 128, cp.async double-buffered K/V.
// 3-term hi/lo (dropped term 2^-24 — effectively exact in fp16).
// grid (P/128, NH, B), 256 threads = 8 warps. Output: single fp16.
// ============================================================================
#define AST 72
#define KVSTG 36864u
#define ATT_SMEM_BYTES (36864 + 2*36864)   // 110592

__global__ __launch_bounds__(256)
void attn_mma(const hf* __restrict__ QKVh, const hf* __restrict__ QKVl,
              hf* __restrict__ Aout) {
    extern __shared__ __align__(16) char smx[];
    const uint32_t sb = smem_u32(smx);

    const int tid = threadIdx.x;
    const int lane = tid & 31;
    const int wid = tid >> 5;          // 0..7
    const int l16 = lane & 15;
    const int qt = blockIdx.x, hh = blockIdx.y, bb = blockIdx.z;
    const int nbase = bb * PSEQ;
    const int hoff  = hh * DKH;

#define KV_ISSUE(kcn) do {                                                    \
    if ((kcn) < 16) {                                                         \
        const uint32_t B = sb + 36864u + (uint32_t)((kcn) & 1) * KVSTG;       \
        _Pragma("unroll")                                                     \
        for (int it = 0; it < 2; it++) {                                      \
            int idx = tid + it*256;                                           \
            int r = idx >> 3;                                                 \
            int c8 = (idx & 7) * 8;                                           \
            const size_t go = (size_t)(nbase + (kcn)*64 + r)*(3*EMB) + hoff + c8; \
            const uint32_t o = (uint32_t)(r*144 + c8*2);                      \
            cpa16(B + o,           QKVh + 512 + go);                          \
            cpa16(B + 9216u + o,   QKVl + 512 + go);                          \
            cpa16(B + 18432u + o,  QKVh + 1024 + go);                         \
            cpa16(B + 27648u + o,  QKVl + 1024 + go);                         \
        }                                                                     \
    }                                                                         \
    asm volatile("cp.async.commit_group;" ::: "memory");                      \
} while (0)

    // ---- Q tile (128x64) via cp.async; grouped with KV chunk 0 ----
#pragma unroll
    for (int it = 0; it < 4; it++) {
        int idx = tid + it*256;
        int r = idx >> 3;
        int c8 = (idx & 7) * 8;
        const size_t go = (size_t)(nbase + qt*128 + r)*(3*EMB) + hoff + c8;
        const uint32_t o = (uint32_t)(r*144 + c8*2);
        cpa16(sb + o,           QKVh + go);
        cpa16(sb + 18432u + o,  QKVl + go);
    }
    KV_ISSUE(0);      // group0 = {Q, KV0}
    KV_ISSUE(1);      // group1 = {KV1}

    float o_acc[8][4];
#pragma unroll
    for (int i = 0; i < 8; i++)
#pragma unroll
        for (int j = 0; j < 4; j++) o_acc[i][j] = 0.f;
    float m_g = -1e30f, m_g8 = -1e30f, l_g = 0.f, l_g8 = 0.f;

    uint32_t qh[4][4], ql[4][4];
    const uint32_t offA = (uint32_t)(((wid*16 + l16) * AST + (lane >> 4) * 8) * 2);
    const uint32_t offBr = (uint32_t)((((l16 & 7)) * AST + ((l16 >> 3)) * 8) * 2);
    const uint32_t offVt = (uint32_t)((((lane & 7) + ((lane >> 3) & 1) * 8)) * AST * 2
                                      + ((lane >> 4) * 8) * 2);

    for (int kc = 0; kc < 16; kc++) {
        asm volatile("cp.async.wait_group 1;" ::: "memory");
        __syncthreads();
        const uint32_t stB = sb + 36864u + (uint32_t)(kc & 1) * KVSTG;

        if (kc == 0) {
#pragma unroll
            for (int ks = 0; ks < 4; ks++) {
                LDSM4(qh[ks], sb + offA + (uint32_t)(ks*32));
                LDSM4(ql[ks], sb + 18432u + offA + (uint32_t)(ks*32));
            }
        }

        // ---- S = Q @ K^T (terms: qh.kh, ql.kh, qh.kl) ----
        float s[8][4];
#pragma unroll
        for (int nt = 0; nt < 8; nt++)
#pragma unroll
            for (int j = 0; j < 4; j++) s[nt][j] = 0.f;
#pragma unroll
        for (int np = 0; np < 4; np++) {
            const int n0 = 2*np, n1 = 2*np + 1;
#pragma unroll
            for (int ks = 0; ks < 4; ks++) {
                uint32_t bh0[2], bl0[2], bh1[2], bl1[2];
                const uint32_t bo0 = offBr + (uint32_t)(n0*8*AST*2 + ks*32);
                const uint32_t bo1 = offBr + (uint32_t)(n1*8*AST*2 + ks*32);
                LDSM2(bh0, stB + bo0);
                LDSM2(bl0, stB + 9216u + bo0);
                LDSM2(bh1, stB + bo1);
                LDSM2(bl1, stB + 9216u + bo1);
                MMA_F16(s[n0], qh[ks], bh0);
                MMA_F16(s[n1], qh[ks], bh1);
                MMA_F16(s[n0], ql[ks], bh0);
                MMA_F16(s[n1], ql[ks], bh1);
                MMA_F16(s[n0], qh[ks], bl0);
                MMA_F16(s[n1], qh[ks], bl1);
            }
        }
#pragma unroll
        for (int nt = 0; nt < 8; nt++) {
            s[nt][0] *= 0.125f; s[nt][1] *= 0.125f;
            s[nt][2] *= 0.125f; s[nt][3] *= 0.125f;
        }

        // ---- online softmax ----
        float cmg = -1e30f, cmg8 = -1e30f;
#pragma unroll
        for (int nt = 0; nt < 8; nt++) {
            cmg  = fmaxf(cmg,  fmaxf(s[nt][0], s[nt][1]));
            cmg8 = fmaxf(cmg8, fmaxf(s[nt][2], s[nt][3]));
        }
        cmg  = fmaxf(cmg,  __shfl_xor_sync(0xffffffffu, cmg, 1));
        cmg  = fmaxf(cmg,  __shfl_xor_sync(0xffffffffu, cmg, 2));
        cmg8 = fmaxf(cmg8, __shfl_xor_sync(0xffffffffu, cmg8, 1));
        cmg8 = fmaxf(cmg8, __shfl_xor_sync(0xffffffffu, cmg8, 2));
        const float mn  = fmaxf(m_g,  cmg);
        const float mn8 = fmaxf(m_g8, cmg8);
        const float alg  = __expf(m_g  - mn);
        const float alg8 = __expf(m_g8 - mn8);
        m_g = mn; m_g8 = mn8;
        float sum = 0.f, sum8 = 0.f;
#pragma unroll
        for (int nt = 0; nt < 8; nt++) {
            s[nt][0] = __expf(s[nt][0] - mn);
            s[nt][1] = __expf(s[nt][1] - mn);
            s[nt][2] = __expf(s[nt][2] - mn8);
            s[nt][3] = __expf(s[nt][3] - mn8);
            sum  += s[nt][0] + s[nt][1];
            sum8 += s[nt][2] + s[nt][3];
        }
        sum  += __shfl_xor_sync(0xffffffffu, sum, 1);
        sum  += __shfl_xor_sync(0xffffffffu, sum, 2);
        sum8 += __shfl_xor_sync(0xffffffffu, sum8, 1);
        sum8 += __shfl_xor_sync(0xffffffffu, sum8, 2);
        l_g  = l_g  * alg  + sum;
        l_g8 = l_g8 * alg8 + sum8;
#pragma unroll
        for (int dt = 0; dt < 8; dt++) {
            o_acc[dt][0] *= alg;  o_acc[dt][1] *= alg;
            o_acc[dt][2] *= alg8; o_acc[dt][3] *= alg8;
        }

        // ---- P fragments from S accums (hi + residual) ----
        uint32_t ph[4][4], pl[4][4];
#pragma unroll
        for (int ks = 0; ks < 4; ks++) {
            float r0, r1;
            ph[ks][0] = pack_hi2(s[2*ks][0],   s[2*ks][1],   r0, r1); pl[ks][0] = pack2(r0, r1);
            ph[ks][1] = pack_hi2(s[2*ks][2],   s[2*ks][3],   r0, r1); pl[ks][1] = pack2(r0, r1);
            ph[ks][2] = pack_hi2(s[2*ks+1][0], s[2*ks+1][1], r0, r1); pl[ks][2] = pack2(r0, r1);
            ph[ks][3] = pack_hi2(s[2*ks+1][2], s[2*ks+1][3], r0, r1); pl[ks][3] = pack2(r0, r1);
        }

        // ---- O += P @ V (terms: ph.vh, pl.vh, ph.vl) ----
#pragma unroll
        for (int dt2 = 0; dt2 < 4; dt2++) {
#pragma unroll
            for (int ks = 0; ks < 4; ks++) {
                const uint32_t va = stB + 18432u + offVt
                    + (uint32_t)(ks*16*AST*2 + dt2*32);
                uint32_t vh4[4], vl4[4];
                LDSM4T(vh4, va);
                LDSM4T(vl4, va + 9216u);
                MMA_F16(o_acc[2*dt2],   ph[ks], vh4);
                MMA_F16(o_acc[2*dt2+1], ph[ks], &vh4[2]);
                MMA_F16(o_acc[2*dt2],   pl[ks], vh4);
                MMA_F16(o_acc[2*dt2+1], pl[ks], &vh4[2]);
                MMA_F16(o_acc[2*dt2],   ph[ks], vl4);
                MMA_F16(o_acc[2*dt2+1], ph[ks], &vl4[2]);
            }
        }
        __syncthreads();   // all reads of stage kc&1 done before refill
        KV_ISSUE(kc + 2);
    }

    // ---- epilogue: single fp16 ----
    const float ig  = 1.f / l_g;
    const float ig8 = 1.f / l_g8;
    const int g = lane >> 2;
    const int r0 = nbase + qt*128 + wid*16 + g;
    const int cb = hoff + 2*(lane & 3);
#pragma unroll
    for (int dt = 0; dt < 8; dt++) {
        *(uint32_t*)(Aout + (size_t)r0*EMB + cb + dt*8) =
            pack2(o_acc[dt][0]*ig,  o_acc[dt][1]*ig);
        *(uint32_t*)(Aout + (size_t)(r0+8)*EMB + cb + dt*8) =
            pack2(o_acc[dt][2]*ig8, o_acc[dt][3]*ig8);
    }
}

// ---------------- weight split / pack kernels --------------------------------
__global__ void split_w4(const float* __restrict__ src, hf* __restrict__ h,
                         hf* __restrict__ l, int n_per_layer, int dst_stride,
                         int dst_off) {
    int idx = blockIdx.x * blockDim.x + threadIdx.x;
    int total4 = (NLAYER * n_per_layer) >> 2;
    if (idx >= total4) return;
    int base = idx * 4;
    int layer = base / n_per_layer;
    int i = base - layer * n_per_layer;
    float4 v = *(const float4*)(src + base);
    float rx, ry;
    uint32_t h01 = pack_hi2(v.x, v.y, rx, ry);
    uint32_t l01 = pack2(rx, ry);
    uint32_t h23 = pack_hi2(v.z, v.w, rx, ry);
    uint32_t l23 = pack2(rx, ry);
    size_t d = (size_t)layer * dst_stride + dst_off + i;
    uint2 hv = {h01, h23}, lv = {l01, l23};
    *(uint2*)(h + d) = hv;
    *(uint2*)(l + d) = lv;
}

__global__ void pack_bqkv(const float* __restrict__ bq, const float* __restrict__ bk,
                          const float* __restrict__ bv, float* __restrict__ dst) {
    int idx = blockIdx.x * blockDim.x + threadIdx.x;
    if (idx >= NLAYER * 3 * EMB) return;
    int l = idx / (3*EMB);
    int n = idx - l * 3*EMB;
    float v;
    if (n < EMB)            v = bq[l*EMB + n];
    else if (n < 2*EMB)     v = bk[l*EMB + n - EMB];
    else                    v = bv[l*EMB + n - 2*EMB];
    dst[idx] = v;
}

// ---------------- positional encoding table --------------------------------
__global__ void pe_kernel(float* __restrict__ pe) {
    int idx = blockIdx.x * blockDim.x + threadIdx.x;
    if (idx >= PSEQ*EMB) return;
    int p = idx >> 9;
    int e = idx & 511;
    int i2 = e >> 1;
    float c = (float)(2*i2) * (-0.017988946039015984f);
    float freqf = (float)exp((double)c);
    float angf  = (float)p * freqf;
    double angle = (double)angf;
    pe[idx] = (e & 1) ? (float)cos(angle) : (float)sin(angle);
}

// ---------------- embedding: conv + linear + PE, writes x + fp16 copy --------
__global__ void embed_kernel(const float* __restrict__ data,
                             const float* __restrict__ cw,
                             const float* __restrict__ cb,
                             const float* __restrict__ lw,
                             const float* __restrict__ lb,
                             const float* __restrict__ pe,
                             float* __restrict__ x,
                             hf* __restrict__ xh) {
    int idx = blockIdx.x * blockDim.x + threadIdx.x;
    if (idx >= NTOK*EMB) return;
    int n = idx >> 9;
    int e = idx & 511;
    int b = n >> 10;
    int p = n & 1023;
    int pi = p >> 5, pj = p & 31;
    const float* dp = data + b*4096 + (pi*2)*64 + pj*2;
    float conv = dp[0]*cw[0] + dp[1]*cw[1] + dp[64]*cw[2] + dp[65]*cw[3] + cb[0];
    float v = conv * lw[e] + lb[e] + pe[p*EMB + e];
    x[idx] = v;
    xh[idx] = __float2half_rn(v);
}

// ---------------- residual add + LayerNorm, writes x + fp16 copy -------------
__global__ __launch_bounds__(128)
void add_ln_kernel(float* __restrict__ x, const float* __restrict__ y,
                   const float* __restrict__ gam, const float* __restrict__ bet,
                   hf* __restrict__ xh) {
    const int row = blockIdx.x;
    const int tid = threadIdx.x;
    const int e = tid * 4;
    float4 xv = *(float4*)&x[(size_t)row*EMB + e];
    float4 yv = *(const float4*)&y[(size_t)row*EMB + e];
    float t0 = xv.x + yv.x, t1 = xv.y + yv.y, t2 = xv.z + yv.z, t3 = xv.w + yv.w;
    float s  = t0 + t1 + t2 + t3;
    float s2 = t0*t0 + t1*t1 + t2*t2 + t3*t3;
#pragma unroll
    for (int off = 16; off > 0; off >>= 1) {
        s  += __shfl_xor_sync(0xffffffffu, s,  off);
        s2 += __shfl_xor_sync(0xffffffffu, s2, off);
    }
    __shared__ float ws[4], ws2[4];
    int w = tid >> 5;
    if ((tid & 31) == 0) { ws[w] = s; ws2[w] = s2; }
    __syncthreads();
    float S  = ws[0] + ws[1] + ws[2] + ws[3];
    float S2 = ws2[0] + ws2[1] + ws2[2] + ws2[3];
    float mu  = S * (1.f/512.f);
    float var = S2 * (1.f/512.f) - mu*mu;
    float rs = rsqrtf(var + 1e-5f);
    float o0 = (t0 - mu)*rs*gam[e+0] + bet[e+0];
    float o1 = (t1 - mu)*rs*gam[e+1] + bet[e+1];
    float o2 = (t2 - mu)*rs*gam[e+2] + bet[e+2];
    float o3 = (t3 - mu)*rs*gam[e+3] + bet[e+3];
    float4 ov = {o0, o1, o2, o3};
    *(float4*)&x[(size_t)row*EMB + e] = ov;
    uint2 hv = {pack2(o0, o1), pack2(o2, o3)};
    *(uint2*)(xh + (size_t)row*EMB + e) = hv;
}

// ---------------- mean pool + final linear ----------------------------------
__global__ __launch_bounds__(512)
void pool_head_kernel(const float* __restrict__ x, const float* __restrict__ Wc,
                      const float* __restrict__ bc, float* __restrict__ out) {
    const int b = blockIdx.x;
    const int e = threadIdx.x;
    float s = 0.f;
    const float* xp = x + (size_t)b*PSEQ*EMB + e;
    for (int p = 0; p < PSEQ; p++) s += xp[(size_t)p*EMB];
    float pooled = s * (1.f/1024.f);
    __shared__ float red[512];
    red[e] = pooled * Wc[e];
    __syncthreads();
    for (int st = 256; st > 0; st >>= 1) {
        if (e < st) red[e] += red[e + st];
        __syncthreads();
    }
    if (e == 0) out[b] = red[0] + bc[0];
}

// ---------------- driver -----------------------------------------------------
extern "C" void kernel_launch(void* const* d_in, const int* in_sizes, int n_in,
                              void* d_out, int out_size) {
    const float* data   = (const float*)d_in[0];
    const float* conv_w = (const float*)d_in[1];
    const float* conv_b = (const float*)d_in[2];
    const float* lin_w  = (const float*)d_in[3];
    const float* lin_b  = (const float*)d_in[4];
    const float* Wq     = (const float*)d_in[5];
    const float* bq     = (const float*)d_in[6];
    const float* Wk     = (const float*)d_in[7];
    const float* bk     = (const float*)d_in[8];
    const float* Wv     = (const float*)d_in[9];
    const float* bv     = (const float*)d_in[10];
    const float* Wo     = (const float*)d_in[11];
    const float* bo     = (const float*)d_in[12];
    const float* ln1_g  = (const float*)d_in[13];
    const float* ln1_b  = (const float*)d_in[14];
    const float* ln2_g  = (const float*)d_in[15];
    const float* ln2_b  = (const float*)d_in[16];
    const float* W1     = (const float*)d_in[17];
    const float* b1     = (const float*)d_in[18];
    const float* W2     = (const float*)d_in[19];
    const float* b2     = (const float*)d_in[20];
    const float* Wc     = (const float*)d_in[21];
    const float* bc     = (const float*)d_in[22];
    float* out = (float*)d_out;

    float *px, *pt, *ppe, *pbqkv;
    hf *pxh, *pqkvh, *pqkvl, *pah, *phh;
    hf *pwqkvh, *pwqkvl, *pwoh, *pwol, *pw1h, *pw1l, *pw2h, *pw2l;
    cudaGetSymbolAddress((void**)&px,  g_x);
    cudaGetSymbolAddress((void**)&pt,  g_t);
    cudaGetSymbolAddress((void**)&ppe, g_pe);
    cudaGetSymbolAddress((void**)&pxh, g_xh);
    cudaGetSymbolAddress((void**)&pqkvh, g_qkvh);
    cudaGetSymbolAddress((void**)&pqkvl, g_qkvl);
    cudaGetSymbolAddress((void**)&pah, g_ah);
    cudaGetSymbolAddress((void**)&phh, g_hh);
    cudaGetSymbolAddress((void**)&pwqkvh, g_wqkvh);
    cudaGetSymbolAddress((void**)&pwqkvl, g_wqkvl);
    cudaGetSymbolAddress((void**)&pwoh, g_woh);
    cudaGetSymbolAddress((void**)&pwol, g_wol);
    cudaGetSymbolAddress((void**)&pw1h, g_w1h);
    cudaGetSymbolAddress((void**)&pw1l, g_w1l);
    cudaGetSymbolAddress((void**)&pw2h, g_w2h);
    cudaGetSymbolAddress((void**)&pw2l, g_w2l);
    cudaGetSymbolAddress((void**)&pbqkv, g_bqkv);

    cudaFuncSetAttribute(gemm_hf<0,0>, cudaFuncAttributeMaxDynamicSharedMemorySize, GSMEM_BYTES);
    cudaFuncSetAttribute(gemm_hf<0,1>, cudaFuncAttributeMaxDynamicSharedMemorySize, GSMEM_BYTES);
    cudaFuncSetAttribute(gemm_hf<1,2>, cudaFuncAttributeMaxDynamicSharedMemorySize, GSMEM_BYTES);
    cudaFuncSetAttribute(attn_mma, cudaFuncAttributeMaxDynamicSharedMemorySize, ATT_SMEM_BYTES);

    // ---- weight/bias packing (once per call) ----
    const int EE = EMB*EMB;          // 262144
    const int FE = FFD*EMB;          // 1048576
    split_w4<<<(NLAYER*EE/4 + 255)/256, 256>>>(Wq, pwqkvh, pwqkvl, EE, 3*EE, 0);
    split_w4<<<(NLAYER*EE/4 + 255)/256, 256>>>(Wk, pwqkvh, pwqkvl, EE, 3*EE, EE);
    split_w4<<<(NLAYER*EE/4 + 255)/256, 256>>>(Wv, pwqkvh, pwqkvl, EE, 3*EE, 2*EE);
    split_w4<<<(NLAYER*EE/4 + 255)/256, 256>>>(Wo, pwoh, pwol, EE, EE, 0);
    split_w4<<<(NLAYER*FE/4 + 255)/256, 256>>>(W1, pw1h, pw1l, FE, FE, 0);
    split_w4<<<(NLAYER*FE/4 + 255)/256, 256>>>(W2, pw2h, pw2l, FE, FE, 0);
    pack_bqkv<<<(NLAYER*3*EMB + 255)/256, 256>>>(bq, bk, bv, pbqkv);

    pe_kernel<<<(PSEQ*EMB + 255)/256, 256>>>(ppe);
    embed_kernel<<<(NTOK*EMB + 255)/256, 256>>>(data, conv_w, conv_b, lin_w, lin_b,
                                                ppe, px, pxh);

    for (int l = 0; l < NLAYER; l++) {
        // fused QKV: [NTOK,512] @ [1536,512]^T -> split fp16 qkv
        gemm_hf<0,1><<<dim3(12,128), 256, GSMEM_BYTES>>>(
            pxh, pwqkvh + (size_t)l*3*EE, pwqkvl + (size_t)l*3*EE,
            pbqkv + l*3*EMB, nullptr, pqkvh, pqkvl, NTOK, 3*EMB, EMB);

        attn_mma<<<dim3(PSEQ/128, NHEAD, BATCH), 256, ATT_SMEM_BYTES>>>(
            pqkvh, pqkvl, pah);

        gemm_hf<0,0><<<dim3(4,128), 256, GSMEM_BYTES>>>(
            pah, pwoh + (size_t)l*EE, pwol + (size_t)l*EE,
            bo + l*EMB, pt, nullptr, nullptr, NTOK, EMB, EMB);
        add_ln_kernel<<<NTOK, 128>>>(px, pt, ln1_g + l*EMB, ln1_b + l*EMB, pxh);

        gemm_hf<1,2><<<dim3(16,128), 256, GSMEM_BYTES>>>(
            pxh, pw1h + (size_t)l*FE, pw1l + (size_t)l*FE,
            b1 + l*FFD, nullptr, phh, nullptr, NTOK, FFD, EMB);

        gemm_hf<0,0><<<dim3(4,128), 256, GSMEM_BYTES>>>(
            phh, pw2h + (size_t)l*FE, pw2l + (size_t)l*FE,
            b2 + l*EMB, pt, nullptr, nullptr, NTOK, EMB, FFD);
        add_ln_kernel<<<NTOK, 128>>>(px, pt, ln2_g + l*EMB, ln2_b + l*EMB, pxh);
    }

    pool_head_kernel<<<BATCH, 512>>>(px, Wc, bc, out);
}

// round 14
// speedup vs baseline: 1.6337x; 1.2900x over previous
#include <cuda_runtime.h>
#include <cuda_fp16.h>
#include <math.h>
#include <stdint.h>

#define BATCH   16
#define PSEQ    1024
#define NTOK    (BATCH*PSEQ)     // 16384
#define EMB     512
#define FFD     2048
#define NLAYER  4
#define NHEAD   8
#define DKH     64

typedef __half hf;

// ---------------- scratch (static device globals; no runtime alloc) ----------
__device__ float g_x [NTOK*EMB];
__device__ float g_t [NTOK*EMB];
__device__ float g_pe[PSEQ*EMB];
__device__ hf g_xh[NTOK*EMB];                       // single fp16 activations
__device__ hf g_qkvh[NTOK*3*EMB], g_qkvl[NTOK*3*EMB];
__device__ hf g_ah[NTOK*EMB];
__device__ hf g_hh[NTOK*FFD];
__device__ hf g_wqkv[NLAYER*3*EMB*EMB];
__device__ hf g_wo[NLAYER*EMB*EMB];
__device__ hf g_w1[NLAYER*FFD*EMB];
__device__ hf g_w2[NLAYER*EMB*FFD];
__device__ float g_bqkv[NLAYER*3*EMB];

// ============================================================================
// helpers
// ============================================================================
static __device__ __forceinline__ uint32_t smem_u32(const void* p) {
    uint32_t a;
    asm("{ .reg .u64 t; cvta.to.shared.u64 t, %1; cvt.u32.u64 %0, t; }"
        : "=r"(a) : "l"(p));
    return a;
}
static __device__ __forceinline__ uint32_t pack2(float a, float b) {
    __half2 t = __floats2half2_rn(a, b);
    return *reinterpret_cast<uint32_t*>(&t);
}
static __device__ __forceinline__ uint32_t pack_hi2(float a, float b, float& ra, float& rb) {
    hf ha = __float2half_rn(a);
    hf hb = __float2half_rn(b);
    ra = a - __half2float(ha);
    rb = b - __half2float(hb);
    return (uint32_t)__half_as_ushort(ha) | ((uint32_t)__half_as_ushort(hb) << 16);
}

#define MMA_F16(d, a, b) \
    asm volatile("mma.sync.aligned.m16n8k16.row.col.f32.f16.f16.f32 " \
        "{%0,%1,%2,%3}, {%4,%5,%6,%7}, {%8,%9}, {%0,%1,%2,%3};" \
        : "+f"((d)[0]), "+f"((d)[1]), "+f"((d)[2]), "+f"((d)[3]) \
        : "r"((a)[0]), "r"((a)[1]), "r"((a)[2]), "r"((a)[3]), \
          "r"((b)[0]), "r"((b)[1]))

#define LDSM4(r, addr) \
    asm volatile("ldmatrix.sync.aligned.m8n8.x4.shared.b16 {%0,%1,%2,%3}, [%4];" \
        : "=r"((r)[0]), "=r"((r)[1]), "=r"((r)[2]), "=r"((r)[3]) : "r"(addr))

#define LDSM4T(r, addr) \
    asm volatile("ldmatrix.sync.aligned.m8n8.x4.trans.shared.b16 {%0,%1,%2,%3}, [%4];" \
        : "=r"((r)[0]), "=r"((r)[1]), "=r"((r)[2]), "=r"((r)[3]) : "r"(addr))

#define LDSM2(r, addr) \
    asm volatile("ldmatrix.sync.aligned.m8n8.x2.shared.b16 {%0,%1}, [%2];" \
        : "=r"((r)[0]), "=r"((r)[1]) : "r"(addr))

static __device__ __forceinline__ void cpa16(uint32_t d, const void* s) {
    asm volatile("cp.async.cg.shared.global [%0], [%1], 16;" :: "r"(d), "l"(s));
}

// swizzled byte offset inside a 128x32-hf tile (rows of 64B = 4x16B chunks)
static __device__ __forceinline__ uint32_t swz32(int r, int c) {
    return (uint32_t)(r * 64 + ((c ^ ((r >> 1) & 3)) << 4));
}

// ============================================================================
// fp16 HMMA GEMM: C = A @ W^T + bias   (single term, fp16 A and W)
// BM=BN=128, BK=32, 2-stage cp.async, 2 CTAs/SM.
// 256 threads = 4(M) x 2(N) warps; warp tile 32x64.
// OUT: 0 = fp32, 1 = split fp16 hi/lo, 2 = single fp16.
// ============================================================================
#define GSTAGE 16384u
#define GSMEM_BYTES (2*GSTAGE)   // 32768

template<int RELU, int OUT>
__global__ __launch_bounds__(256, 2)
void gemm_hf(const hf* __restrict__ A, const hf* __restrict__ W,
             const float* __restrict__ bias,
             float* __restrict__ Cf, hf* __restrict__ Ch, hf* __restrict__ Cl,
             int M, int N, int K) {
    extern __shared__ __align__(16) char dsm[];
    const uint32_t sb = smem_u32(dsm);
    const int tid = threadIdx.x, lane = tid & 31, wid = tid >> 5;
    const int wm = wid & 3, wn = wid >> 2;
    const int bx = blockIdx.x, by = blockIdx.y;
    const int KT = K >> 5;

    float acc[2][8][4];
#pragma unroll
    for (int i = 0; i < 2; i++)
#pragma unroll
        for (int j = 0; j < 8; j++)
#pragma unroll
            for (int q = 0; q < 4; q++) acc[i][j][q] = 0.f;

    const int cr = tid >> 2, cc = tid & 3;
    const size_t aoff = (size_t)(by*128 + cr)*K + cc*8;
    const size_t woff = (size_t)(bx*128 + cr)*K + cc*8;
    const uint32_t so0 = swz32(cr, cc), so1 = swz32(cr + 64, cc);

    const int l16 = lane & 15;
    const int rB = (lane & 7) + ((lane >> 4) << 3);
    const int cB = (lane >> 3) & 1;

#define G_ISSUE(ktn) do {                                                     \
    if ((ktn) < KT) {                                                         \
        const uint32_t stb = sb + (uint32_t)((ktn) & 1) * GSTAGE;             \
        const int ko = (ktn) * 32;                                            \
        cpa16(stb + so0,          A + aoff + ko);                             \
        cpa16(stb + so1,          A + aoff + (size_t)64*K + ko);              \
        cpa16(stb + 8192u + so0,  W + woff + ko);                             \
        cpa16(stb + 8192u + so1,  W + woff + (size_t)64*K + ko);              \
    }                                                                         \
    asm volatile("cp.async.commit_group;" ::: "memory");                      \
} while (0)

    G_ISSUE(0);

    for (int kt = 0; kt < KT; kt++) {
        G_ISSUE(kt + 1);
        asm volatile("cp.async.wait_group 1;" ::: "memory");
        __syncthreads();

        const uint32_t stb = sb + (uint32_t)(kt & 1) * GSTAGE;
#pragma unroll
        for (int ks = 0; ks < 2; ks++) {
            uint32_t ah[2][4];
            uint32_t bh[4][4];
#pragma unroll
            for (int mt = 0; mt < 2; mt++) {
                const uint32_t oa = stb + swz32(wm*32 + mt*16 + l16, ks*2 + (lane >> 4));
                LDSM4(ah[mt], oa);
            }
#pragma unroll
            for (int ntp = 0; ntp < 4; ntp++) {
                const uint32_t ob = stb + 8192u + swz32(wn*64 + ntp*16 + rB, ks*2 + cB);
                LDSM4(bh[ntp], ob);
            }
#pragma unroll
            for (int ntp = 0; ntp < 4; ntp++)
#pragma unroll
                for (int mt = 0; mt < 2; mt++) {
                    MMA_F16(acc[mt][2*ntp],   ah[mt], bh[ntp]);
                    MMA_F16(acc[mt][2*ntp+1], ah[mt], &bh[ntp][2]);
                }
        }
        __syncthreads();   // reads of buffer kt&1 done before it is re-filled
    }

    const int rbase = by*128 + wm*32 + (lane >> 2);
    const int cbase = bx*128 + wn*64 + 2*(lane & 3);
#pragma unroll
    for (int mt = 0; mt < 2; mt++) {
#pragma unroll
        for (int nt = 0; nt < 8; nt++) {
            const int row = rbase + mt*16;
            const int col = cbase + nt*8;
            const float b0 = bias[col], b1 = bias[col+1];
            float v0x = acc[mt][nt][0] + b0, v0y = acc[mt][nt][1] + b1;
            float v1x = acc[mt][nt][2] + b0, v1y = acc[mt][nt][3] + b1;
            if (RELU) {
                v0x = fmaxf(v0x, 0.f); v0y = fmaxf(v0y, 0.f);
                v1x = fmaxf(v1x, 0.f); v1y = fmaxf(v1y, 0.f);
            }
            if (OUT == 1) {
                float rx, ry;
                uint32_t h = pack_hi2(v0x, v0y, rx, ry);
                uint32_t l = pack2(rx, ry);
                *(uint32_t*)(Ch + (size_t)row*N + col) = h;
                *(uint32_t*)(Cl + (size_t)row*N + col) = l;
                h = pack_hi2(v1x, v1y, rx, ry);
                l = pack2(rx, ry);
                *(uint32_t*)(Ch + (size_t)(row+8)*N + col) = h;
                *(uint32_t*)(Cl + (size_t)(row+8)*N + col) = l;
            } else if (OUT == 2) {
                *(uint32_t*)(Ch + (size_t)row*N + col)     = pack2(v0x, v0y);
                *(uint32_t*)(Ch + (size_t)(row+8)*N + col) = pack2(v1x, v1y);
            } else {
                float2 a = {v0x, v0y}, b = {v1x, v1y};
                *(float2*)(Cf + (size_t)row*N + col)     = a;
                *(float2*)(Cf + (size_t)(row+8)*N + col) = b;
            }
        }
    }
}

// ============================================================================
// fp16 HMMA flash attention, Q-tile 128, cp.async double-buffered K/V.
// 3-term hi/lo (dropped term 2^-24 — effectively exact in fp16).
// grid (P/128, NH, B), 256 threads = 8 warps. Output: single fp16.
// ============================================================================
#define AST 72
#define KVSTG 36864u
#define ATT_SMEM_BYTES (36864 + 2*36864)   // 110592

__global__ __launch_bounds__(256)
void attn_mma(const hf* __restrict__ QKVh, const hf* __restrict__ QKVl,
              hf* __restrict__ Aout) {
    extern __shared__ __align__(16) char smx[];
    const uint32_t sb = smem_u32(smx);

    const int tid = threadIdx.x;
    const int lane = tid & 31;
    const int wid = tid >> 5;          // 0..7
    const int l16 = lane & 15;
    const int qt = blockIdx.x, hh = blockIdx.y, bb = blockIdx.z;
    const int nbase = bb * PSEQ;
    const int hoff  = hh * DKH;

#define KV_ISSUE(kcn) do {                                                    \
    if ((kcn) < 16) {                                                         \
        const uint32_t B = sb + 36864u + (uint32_t)((kcn) & 1) * KVSTG;       \
        _Pragma("unroll")                                                     \
        for (int it = 0; it < 2; it++) {                                      \
            int idx = tid + it*256;                                           \
            int r = idx >> 3;                                                 \
            int c8 = (idx & 7) * 8;                                           \
            const size_t go = (size_t)(nbase + (kcn)*64 + r)*(3*EMB) + hoff + c8; \
            const uint32_t o = (uint32_t)(r*144 + c8*2);                      \
            cpa16(B + o,           QKVh + 512 + go);                          \
            cpa16(B + 9216u + o,   QKVl + 512 + go);                          \
            cpa16(B + 18432u + o,  QKVh + 1024 + go);                         \
            cpa16(B + 27648u + o,  QKVl + 1024 + go);                         \
        }                                                                     \
    }                                                                         \
    asm volatile("cp.async.commit_group;" ::: "memory");                      \
} while (0)

    // ---- Q tile (128x64) via cp.async; grouped with KV chunk 0 ----
#pragma unroll
    for (int it = 0; it < 4; it++) {
        int idx = tid + it*256;
        int r = idx >> 3;
        int c8 = (idx & 7) * 8;
        const size_t go = (size_t)(nbase + qt*128 + r)*(3*EMB) + hoff + c8;
        const uint32_t o = (uint32_t)(r*144 + c8*2);
        cpa16(sb + o,           QKVh + go);
        cpa16(sb + 18432u + o,  QKVl + go);
    }
    KV_ISSUE(0);      // group0 = {Q, KV0}
    KV_ISSUE(1);      // group1 = {KV1}

    float o_acc[8][4];
#pragma unroll
    for (int i = 0; i < 8; i++)
#pragma unroll
        for (int j = 0; j < 4; j++) o_acc[i][j] = 0.f;
    float m_g = -1e30f, m_g8 = -1e30f, l_g = 0.f, l_g8 = 0.f;

    uint32_t qh[4][4], ql[4][4];
    const uint32_t offA = (uint32_t)(((wid*16 + l16) * AST + (lane >> 4) * 8) * 2);
    const uint32_t offBr = (uint32_t)((((l16 & 7)) * AST + ((l16 >> 3)) * 8) * 2);
    const uint32_t offVt = (uint32_t)((((lane & 7) + ((lane >> 3) & 1) * 8)) * AST * 2
                                      + ((lane >> 4) * 8) * 2);

    for (int kc = 0; kc < 16; kc++) {
        asm volatile("cp.async.wait_group 1;" ::: "memory");
        __syncthreads();
        const uint32_t stB = sb + 36864u + (uint32_t)(kc & 1) * KVSTG;

        if (kc == 0) {
#pragma unroll
            for (int ks = 0; ks < 4; ks++) {
                LDSM4(qh[ks], sb + offA + (uint32_t)(ks*32));
                LDSM4(ql[ks], sb + 18432u + offA + (uint32_t)(ks*32));
            }
        }

        // ---- S = Q @ K^T (terms: qh.kh, ql.kh, qh.kl) ----
        float s[8][4];
#pragma unroll
        for (int nt = 0; nt < 8; nt++)
#pragma unroll
            for (int j = 0; j < 4; j++) s[nt][j] = 0.f;
#pragma unroll
        for (int np = 0; np < 4; np++) {
            const int n0 = 2*np, n1 = 2*np + 1;
#pragma unroll
            for (int ks = 0; ks < 4; ks++) {
                uint32_t bh0[2], bl0[2], bh1[2], bl1[2];
                const uint32_t bo0 = offBr + (uint32_t)(n0*8*AST*2 + ks*32);
                const uint32_t bo1 = offBr + (uint32_t)(n1*8*AST*2 + ks*32);
                LDSM2(bh0, stB + bo0);
                LDSM2(bl0, stB + 9216u + bo0);
                LDSM2(bh1, stB + bo1);
                LDSM2(bl1, stB + 9216u + bo1);
                MMA_F16(s[n0], qh[ks], bh0);
                MMA_F16(s[n1], qh[ks], bh1);
                MMA_F16(s[n0], ql[ks], bh0);
                MMA_F16(s[n1], ql[ks], bh1);
                MMA_F16(s[n0], qh[ks], bl0);
                MMA_F16(s[n1], qh[ks], bl1);
            }
        }
#pragma unroll
        for (int nt = 0; nt < 8; nt++) {
            s[nt][0] *= 0.125f; s[nt][1] *= 0.125f;
            s[nt][2] *= 0.125f; s[nt][3] *= 0.125f;
        }

        // ---- online softmax ----
        float cmg = -1e30f, cmg8 = -1e30f;
#pragma unroll
        for (int nt = 0; nt < 8; nt++) {
            cmg  = fmaxf(cmg,  fmaxf(s[nt][0], s[nt][1]));
            cmg8 = fmaxf(cmg8, fmaxf(s[nt][2], s[nt][3]));
        }
        cmg  = fmaxf(cmg,  __shfl_xor_sync(0xffffffffu, cmg, 1));
        cmg  = fmaxf(cmg,  __shfl_xor_sync(0xffffffffu, cmg, 2));
        cmg8 = fmaxf(cmg8, __shfl_xor_sync(0xffffffffu, cmg8, 1));
        cmg8 = fmaxf(cmg8, __shfl_xor_sync(0xffffffffu, cmg8, 2));
        const float mn  = fmaxf(m_g,  cmg);
        const float mn8 = fmaxf(m_g8, cmg8);
        const float alg  = __expf(m_g  - mn);
        const float alg8 = __expf(m_g8 - mn8);
        m_g = mn; m_g8 = mn8;
        float sum = 0.f, sum8 = 0.f;
#pragma unroll
        for (int nt = 0; nt < 8; nt++) {
            s[nt][0] = __expf(s[nt][0] - mn);
            s[nt][1] = __expf(s[nt][1] - mn);
            s[nt][2] = __expf(s[nt][2] - mn8);
            s[nt][3] = __expf(s[nt][3] - mn8);
            sum  += s[nt][0] + s[nt][1];
            sum8 += s[nt][2] + s[nt][3];
        }
        sum  += __shfl_xor_sync(0xffffffffu, sum, 1);
        sum  += __shfl_xor_sync(0xffffffffu, sum, 2);
        sum8 += __shfl_xor_sync(0xffffffffu, sum8, 1);
        sum8 += __shfl_xor_sync(0xffffffffu, sum8, 2);
        l_g  = l_g  * alg  + sum;
        l_g8 = l_g8 * alg8 + sum8;
#pragma unroll
        for (int dt = 0; dt < 8; dt++) {
            o_acc[dt][0] *= alg;  o_acc[dt][1] *= alg;
            o_acc[dt][2] *= alg8; o_acc[dt][3] *= alg8;
        }

        // ---- P fragments from S accums (hi + residual) ----
        uint32_t ph[4][4], pl[4][4];
#pragma unroll
        for (int ks = 0; ks < 4; ks++) {
            float r0, r1;
            ph[ks][0] = pack_hi2(s[2*ks][0],   s[2*ks][1],   r0, r1); pl[ks][0] = pack2(r0, r1);
            ph[ks][1] = pack_hi2(s[2*ks][2],   s[2*ks][3],   r0, r1); pl[ks][1] = pack2(r0, r1);
            ph[ks][2] = pack_hi2(s[2*ks+1][0], s[2*ks+1][1], r0, r1); pl[ks][2] = pack2(r0, r1);
            ph[ks][3] = pack_hi2(s[2*ks+1][2], s[2*ks+1][3], r0, r1); pl[ks][3] = pack2(r0, r1);
        }

        // ---- O += P @ V (terms: ph.vh, pl.vh, ph.vl) ----
#pragma unroll
        for (int dt2 = 0; dt2 < 4; dt2++) {
#pragma unroll
            for (int ks = 0; ks < 4; ks++) {
                const uint32_t va = stB + 18432u + offVt
                    + (uint32_t)(ks*16*AST*2 + dt2*32);
                uint32_t vh4[4], vl4[4];
                LDSM4T(vh4, va);
                LDSM4T(vl4, va + 9216u);
                MMA_F16(o_acc[2*dt2],   ph[ks], vh4);
                MMA_F16(o_acc[2*dt2+1], ph[ks], &vh4[2]);
                MMA_F16(o_acc[2*dt2],   pl[ks], vh4);
                MMA_F16(o_acc[2*dt2+1], pl[ks], &vh4[2]);
                MMA_F16(o_acc[2*dt2],   ph[ks], vl4);
                MMA_F16(o_acc[2*dt2+1], ph[ks], &vl4[2]);
            }
        }
        __syncthreads();   // all reads of stage kc&1 done before refill
        KV_ISSUE(kc + 2);
    }

    // ---- epilogue: single fp16 ----
    const float ig  = 1.f / l_g;
    const float ig8 = 1.f / l_g8;
    const int g = lane >> 2;
    const int r0 = nbase + qt*128 + wid*16 + g;
    const int cb = hoff + 2*(lane & 3);
#pragma unroll
    for (int dt = 0; dt < 8; dt++) {
        *(uint32_t*)(Aout + (size_t)r0*EMB + cb + dt*8) =
            pack2(o_acc[dt][0]*ig,  o_acc[dt][1]*ig);
        *(uint32_t*)(Aout + (size_t)(r0+8)*EMB + cb + dt*8) =
            pack2(o_acc[dt][2]*ig8, o_acc[dt][3]*ig8);
    }
}

// ---------------- weight convert / pack kernels ------------------------------
__global__ void conv_w4(const float* __restrict__ src, hf* __restrict__ h,
                        int n_per_layer, int dst_stride, int dst_off) {
    int idx = blockIdx.x * blockDim.x + threadIdx.x;
    int total4 = (NLAYER * n_per_layer) >> 2;
    if (idx >= total4) return;
    int base = idx * 4;
    int layer = base / n_per_layer;
    int i = base - layer * n_per_layer;
    float4 v = *(const float4*)(src + base);
    size_t d = (size_t)layer * dst_stride + dst_off + i;
    uint2 hv = {pack2(v.x, v.y), pack2(v.z, v.w)};
    *(uint2*)(h + d) = hv;
}

__global__ void pack_bqkv(const float* __restrict__ bq, const float* __restrict__ bk,
                          const float* __restrict__ bv, float* __restrict__ dst) {
    int idx = blockIdx.x * blockDim.x + threadIdx.x;
    if (idx >= NLAYER * 3 * EMB) return;
    int l = idx / (3*EMB);
    int n = idx - l * 3*EMB;
    float v;
    if (n < EMB)            v = bq[l*EMB + n];
    else if (n < 2*EMB)     v = bk[l*EMB + n - EMB];
    else                    v = bv[l*EMB + n - 2*EMB];
    dst[idx] = v;
}

// ---------------- positional encoding table --------------------------------
__global__ void pe_kernel(float* __restrict__ pe) {
    int idx = blockIdx.x * blockDim.x + threadIdx.x;
    if (idx >= PSEQ*EMB) return;
    int p = idx >> 9;
    int e = idx & 511;
    int i2 = e >> 1;
    float c = (float)(2*i2) * (-0.017988946039015984f);
    float freqf = (float)exp((double)c);
    float angf  = (float)p * freqf;
    double angle = (double)angf;
    pe[idx] = (e & 1) ? (float)cos(angle) : (float)sin(angle);
}

// ---------------- embedding: conv + linear + PE, writes x + fp16 copy --------
__global__ void embed_kernel(const float* __restrict__ data,
                             const float* __restrict__ cw,
                             const float* __restrict__ cb,
                             const float* __restrict__ lw,
                             const float* __restrict__ lb,
                             const float* __restrict__ pe,
                             float* __restrict__ x,
                             hf* __restrict__ xh) {
    int idx = blockIdx.x * blockDim.x + threadIdx.x;
    if (idx >= NTOK*EMB) return;
    int n = idx >> 9;
    int e = idx & 511;
    int b = n >> 10;
    int p = n & 1023;
    int pi = p >> 5, pj = p & 31;
    const float* dp = data + b*4096 + (pi*2)*64 + pj*2;
    float conv = dp[0]*cw[0] + dp[1]*cw[1] + dp[64]*cw[2] + dp[65]*cw[3] + cb[0];
    float v = conv * lw[e] + lb[e] + pe[p*EMB + e];
    x[idx] = v;
    xh[idx] = __float2half_rn(v);
}

// ---------------- residual add + LayerNorm, writes x + fp16 copy -------------
__global__ __launch_bounds__(128)
void add_ln_kernel(float* __restrict__ x, const float* __restrict__ y,
                   const float* __restrict__ gam, const float* __restrict__ bet,
                   hf* __restrict__ xh) {
    const int row = blockIdx.x;
    const int tid = threadIdx.x;
    const int e = tid * 4;
    float4 xv = *(float4*)&x[(size_t)row*EMB + e];
    float4 yv = *(const float4*)&y[(size_t)row*EMB + e];
    float t0 = xv.x + yv.x, t1 = xv.y + yv.y, t2 = xv.z + yv.z, t3 = xv.w + yv.w;
    float s  = t0 + t1 + t2 + t3;
    float s2 = t0*t0 + t1*t1 + t2*t2 + t3*t3;
#pragma unroll
    for (int off = 16; off > 0; off >>= 1) {
        s  += __shfl_xor_sync(0xffffffffu, s,  off);
        s2 += __shfl_xor_sync(0xffffffffu, s2, off);
    }
    __shared__ float ws[4], ws2[4];
    int w = tid >> 5;
    if ((tid & 31) == 0) { ws[w] = s; ws2[w] = s2; }
    __syncthreads();
    float S  = ws[0] + ws[1] + ws[2] + ws[3];
    float S2 = ws2[0] + ws2[1] + ws2[2] + ws2[3];
    float mu  = S * (1.f/512.f);
    float var = S2 * (1.f/512.f) - mu*mu;
    float rs = rsqrtf(var + 1e-5f);
    float o0 = (t0 - mu)*rs*gam[e+0] + bet[e+0];
    float o1 = (t1 - mu)*rs*gam[e+1] + bet[e+1];
    float o2 = (t2 - mu)*rs*gam[e+2] + bet[e+2];
    float o3 = (t3 - mu)*rs*gam[e+3] + bet[e+3];
    float4 ov = {o0, o1, o2, o3};
    *(float4*)&x[(size_t)row*EMB + e] = ov;
    uint2 hv = {pack2(o0, o1), pack2(o2, o3)};
    *(uint2*)(xh + (size_t)row*EMB + e) = hv;
}

// ---------------- mean pool + final linear ----------------------------------
__global__ __launch_bounds__(512)
void pool_head_kernel(const float* __restrict__ x, const float* __restrict__ Wc,
                      const float* __restrict__ bc, float* __restrict__ out) {
    const int b = blockIdx.x;
    const int e = threadIdx.x;
    float s = 0.f;
    const float* xp = x + (size_t)b*PSEQ*EMB + e;
    for (int p = 0; p < PSEQ; p++) s += xp[(size_t)p*EMB];
    float pooled = s * (1.f/1024.f);
    __shared__ float red[512];
    red[e] = pooled * Wc[e];
    __syncthreads();
    for (int st = 256; st > 0; st >>= 1) {
        if (e < st) red[e] += red[e + st];
        __syncthreads();
    }
    if (e == 0) out[b] = red[0] + bc[0];
}

// ---------------- driver -----------------------------------------------------
extern "C" void kernel_launch(void* const* d_in, const int* in_sizes, int n_in,
                              void* d_out, int out_size) {
    const float* data   = (const float*)d_in[0];
    const float* conv_w = (const float*)d_in[1];
    const float* conv_b = (const float*)d_in[2];
    const float* lin_w  = (const float*)d_in[3];
    const float* lin_b  = (const float*)d_in[4];
    const float* Wq     = (const float*)d_in[5];
    const float* bq     = (const float*)d_in[6];
    const float* Wk     = (const float*)d_in[7];
    const float* bk     = (const float*)d_in[8];
    const float* Wv     = (const float*)d_in[9];
    const float* bv     = (const float*)d_in[10];
    const float* Wo     = (const float*)d_in[11];
    const float* bo     = (const float*)d_in[12];
    const float* ln1_g  = (const float*)d_in[13];
    const float* ln1_b  = (const float*)d_in[14];
    const float* ln2_g  = (const float*)d_in[15];
    const float* ln2_b  = (const float*)d_in[16];
    const float* W1     = (const float*)d_in[17];
    const float* b1     = (const float*)d_in[18];
    const float* W2     = (const float*)d_in[19];
    const float* b2     = (const float*)d_in[20];
    const float* Wc     = (const float*)d_in[21];
    const float* bc     = (const float*)d_in[22];
    float* out = (float*)d_out;

    float *px, *pt, *ppe, *pbqkv;
    hf *pxh, *pqkvh, *pqkvl, *pah, *phh;
    hf *pwqkv, *pwo, *pw1, *pw2;
    cudaGetSymbolAddress((void**)&px,  g_x);
    cudaGetSymbolAddress((void**)&pt,  g_t);
    cudaGetSymbolAddress((void**)&ppe, g_pe);
    cudaGetSymbolAddress((void**)&pxh, g_xh);
    cudaGetSymbolAddress((void**)&pqkvh, g_qkvh);
    cudaGetSymbolAddress((void**)&pqkvl, g_qkvl);
    cudaGetSymbolAddress((void**)&pah, g_ah);
    cudaGetSymbolAddress((void**)&phh, g_hh);
    cudaGetSymbolAddress((void**)&pwqkv, g_wqkv);
    cudaGetSymbolAddress((void**)&pwo, g_wo);
    cudaGetSymbolAddress((void**)&pw1, g_w1);
    cudaGetSymbolAddress((void**)&pw2, g_w2);
    cudaGetSymbolAddress((void**)&pbqkv, g_bqkv);

    cudaFuncSetAttribute(gemm_hf<0,0>, cudaFuncAttributeMaxDynamicSharedMemorySize, GSMEM_BYTES);
    cudaFuncSetAttribute(gemm_hf<0,1>, cudaFuncAttributeMaxDynamicSharedMemorySize, GSMEM_BYTES);
    cudaFuncSetAttribute(gemm_hf<1,2>, cudaFuncAttributeMaxDynamicSharedMemorySize, GSMEM_BYTES);
    cudaFuncSetAttribute(attn_mma, cudaFuncAttributeMaxDynamicSharedMemorySize, ATT_SMEM_BYTES);

    // ---- weight/bias packing (once per call) ----
    const int EE = EMB*EMB;          // 262144
    const int FE = FFD*EMB;          // 1048576
    conv_w4<<<(NLAYER*EE/4 + 255)/256, 256>>>(Wq, pwqkv, EE, 3*EE, 0);
    conv_w4<<<(NLAYER*EE/4 + 255)/256, 256>>>(Wk, pwqkv, EE, 3*EE, EE);
    conv_w4<<<(NLAYER*EE/4 + 255)/256, 256>>>(Wv, pwqkv, EE, 3*EE, 2*EE);
    conv_w4<<<(NLAYER*EE/4 + 255)/256, 256>>>(Wo, pwo, EE, EE, 0);
    conv_w4<<<(NLAYER*FE/4 + 255)/256, 256>>>(W1, pw1, FE, FE, 0);
    conv_w4<<<(NLAYER*FE/4 + 255)/256, 256>>>(W2, pw2, FE, FE, 0);
    pack_bqkv<<<(NLAYER*3*EMB + 255)/256, 256>>>(bq, bk, bv, pbqkv);

    pe_kernel<<<(PSEQ*EMB + 255)/256, 256>>>(ppe);
    embed_kernel<<<(NTOK*EMB + 255)/256, 256>>>(data, conv_w, conv_b, lin_w, lin_b,
                                                ppe, px, pxh);

    for (int l = 0; l < NLAYER; l++) {
        // fused QKV: [NTOK,512] @ [1536,512]^T -> split fp16 qkv
        gemm_hf<0,1><<<dim3(12,128), 256, GSMEM_BYTES>>>(
            pxh, pwqkv + (size_t)l*3*EE,
            pbqkv + l*3*EMB, nullptr, pqkvh, pqkvl, NTOK, 3*EMB, EMB);

        attn_mma<<<dim3(PSEQ/128, NHEAD, BATCH), 256, ATT_SMEM_BYTES>>>(
            pqkvh, pqkvl, pah);

        gemm_hf<0,0><<<dim3(4,128), 256, GSMEM_BYTES>>>(
            pah, pwo + (size_t)l*EE,
            bo + l*EMB, pt, nullptr, nullptr, NTOK, EMB, EMB);
        add_ln_kernel<<<NTOK, 128>>>(px, pt, ln1_g + l*EMB, ln1_b + l*EMB, pxh);

        gemm_hf<1,2><<<dim3(16,128), 256, GSMEM_BYTES>>>(
            pxh, pw1 + (size_t)l*FE,
            b1 + l*FFD, nullptr, phh, nullptr, NTOK, FFD, EMB);

        gemm_hf<0,0><<<dim3(4,128), 256, GSMEM_BYTES>>>(
            phh, pw2 + (size_t)l*FE,
            b2 + l*EMB, pt, nullptr, nullptr, NTOK, EMB, FFD);
        add_ln_kernel<<<NTOK, 128>>>(px, pt, ln2_g + l*EMB, ln2_b + l*EMB, pxh);
    }

    pool_head_kernel<<<BATCH, 512>>>(px, Wc, bc, out);
}

// round 15
// speedup vs baseline: 2.3530x; 1.4403x over previous
#include <cuda_runtime.h>
#include <cuda_fp16.h>
#include <math.h>
#include <stdint.h>

#define BATCH   16
#define PSEQ    1024
#define NTOK    (BATCH*PSEQ)     // 16384
#define EMB     512
#define FFD     2048
#define NLAYER  4
#define NHEAD   8
#define DKH     64

typedef __half hf;

// ---------------- scratch (static device globals; no runtime alloc) ----------
__device__ float g_x [NTOK*EMB];
__device__ float g_t [NTOK*EMB];
__device__ float g_pe[PSEQ*EMB];
__device__ hf g_xh[NTOK*EMB];
__device__ hf g_qkv[NTOK*3*EMB];
__device__ hf g_ah[NTOK*EMB];
__device__ hf g_hh[NTOK*FFD];
__device__ hf g_wqkv[NLAYER*3*EMB*EMB];
__device__ hf g_wo[NLAYER*EMB*EMB];
__device__ hf g_w1[NLAYER*FFD*EMB];
__device__ hf g_w2[NLAYER*EMB*FFD];
__device__ float g_bqkv[NLAYER*3*EMB];

// ============================================================================
// helpers
// ============================================================================
static __device__ __forceinline__ uint32_t smem_u32(const void* p) {
    uint32_t a;
    asm("{ .reg .u64 t; cvta.to.shared.u64 t, %1; cvt.u32.u64 %0, t; }"
        : "=r"(a) : "l"(p));
    return a;
}
static __device__ __forceinline__ uint32_t pack2(float a, float b) {
    __half2 t = __floats2half2_rn(a, b);
    return *reinterpret_cast<uint32_t*>(&t);
}

#define MMA_F16(d, a, b) \
    asm volatile("mma.sync.aligned.m16n8k16.row.col.f32.f16.f16.f32 " \
        "{%0,%1,%2,%3}, {%4,%5,%6,%7}, {%8,%9}, {%0,%1,%2,%3};" \
        : "+f"((d)[0]), "+f"((d)[1]), "+f"((d)[2]), "+f"((d)[3]) \
        : "r"((a)[0]), "r"((a)[1]), "r"((a)[2]), "r"((a)[3]), \
          "r"((b)[0]), "r"((b)[1]))

#define LDSM4(r, addr) \
    asm volatile("ldmatrix.sync.aligned.m8n8.x4.shared.b16 {%0,%1,%2,%3}, [%4];" \
        : "=r"((r)[0]), "=r"((r)[1]), "=r"((r)[2]), "=r"((r)[3]) : "r"(addr))

#define LDSM4T(r, addr) \
    asm volatile("ldmatrix.sync.aligned.m8n8.x4.trans.shared.b16 {%0,%1,%2,%3}, [%4];" \
        : "=r"((r)[0]), "=r"((r)[1]), "=r"((r)[2]), "=r"((r)[3]) : "r"(addr))

#define LDSM2(r, addr) \
    asm volatile("ldmatrix.sync.aligned.m8n8.x2.shared.b16 {%0,%1}, [%2];" \
        : "=r"((r)[0]), "=r"((r)[1]) : "r"(addr))

static __device__ __forceinline__ void cpa16(uint32_t d, const void* s) {
    asm volatile("cp.async.cg.shared.global [%0], [%1], 16;" :: "r"(d), "l"(s));
}

// swizzled byte offset inside a 128x32-hf tile (rows of 64B = 4x16B chunks)
static __device__ __forceinline__ uint32_t swz32(int r, int c) {
    return (uint32_t)(r * 64 + ((c ^ ((r >> 1) & 3)) << 4));
}

// ============================================================================
// fp16 HMMA GEMM: C = A @ W^T + bias   (single term, fp16 A and W)
// BM=BN=128, BK=32, 2-stage cp.async, 2 CTAs/SM.
// OUT: 0 = fp32, 2 = single fp16.
// ============================================================================
#define GSTAGE 16384u
#define GSMEM_BYTES (2*GSTAGE)   // 32768

template<int RELU, int OUT>
__global__ __launch_bounds__(256, 2)
void gemm_hf(const hf* __restrict__ A, const hf* __restrict__ W,
             const float* __restrict__ bias,
             float* __restrict__ Cf, hf* __restrict__ Ch,
             int M, int N, int K) {
    extern __shared__ __align__(16) char dsm[];
    const uint32_t sb = smem_u32(dsm);
    const int tid = threadIdx.x, lane = tid & 31, wid = tid >> 5;
    const int wm = wid & 3, wn = wid >> 2;
    const int bx = blockIdx.x, by = blockIdx.y;
    const int KT = K >> 5;

    float acc[2][8][4];
#pragma unroll
    for (int i = 0; i < 2; i++)
#pragma unroll
        for (int j = 0; j < 8; j++)
#pragma unroll
            for (int q = 0; q < 4; q++) acc[i][j][q] = 0.f;

    const int cr = tid >> 2, cc = tid & 3;
    const size_t aoff = (size_t)(by*128 + cr)*K + cc*8;
    const size_t woff = (size_t)(bx*128 + cr)*K + cc*8;
    const uint32_t so0 = swz32(cr, cc), so1 = swz32(cr + 64, cc);

    const int l16 = lane & 15;
    const int rB = (lane & 7) + ((lane >> 4) << 3);
    const int cB = (lane >> 3) & 1;

#define G_ISSUE(ktn) do {                                                     \
    if ((ktn) < KT) {                                                         \
        const uint32_t stb = sb + (uint32_t)((ktn) & 1) * GSTAGE;             \
        const int ko = (ktn) * 32;                                            \
        cpa16(stb + so0,          A + aoff + ko);                             \
        cpa16(stb + so1,          A + aoff + (size_t)64*K + ko);              \
        cpa16(stb + 8192u + so0,  W + woff + ko);                             \
        cpa16(stb + 8192u + so1,  W + woff + (size_t)64*K + ko);              \
    }                                                                         \
    asm volatile("cp.async.commit_group;" ::: "memory");                      \
} while (0)

    G_ISSUE(0);

    for (int kt = 0; kt < KT; kt++) {
        G_ISSUE(kt + 1);
        asm volatile("cp.async.wait_group 1;" ::: "memory");
        __syncthreads();

        const uint32_t stb = sb + (uint32_t)(kt & 1) * GSTAGE;
#pragma unroll
        for (int ks = 0; ks < 2; ks++) {
            uint32_t ah[2][4];
            uint32_t bh[4][4];
#pragma unroll
            for (int mt = 0; mt < 2; mt++) {
                const uint32_t oa = stb + swz32(wm*32 + mt*16 + l16, ks*2 + (lane >> 4));
                LDSM4(ah[mt], oa);
            }
#pragma unroll
            for (int ntp = 0; ntp < 4; ntp++) {
                const uint32_t ob = stb + 8192u + swz32(wn*64 + ntp*16 + rB, ks*2 + cB);
                LDSM4(bh[ntp], ob);
            }
#pragma unroll
            for (int ntp = 0; ntp < 4; ntp++)
#pragma unroll
                for (int mt = 0; mt < 2; mt++) {
                    MMA_F16(acc[mt][2*ntp],   ah[mt], bh[ntp]);
                    MMA_F16(acc[mt][2*ntp+1], ah[mt], &bh[ntp][2]);
                }
        }
        __syncthreads();   // reads of buffer kt&1 done before it is re-filled
    }

    const int rbase = by*128 + wm*32 + (lane >> 2);
    const int cbase = bx*128 + wn*64 + 2*(lane & 3);
#pragma unroll
    for (int mt = 0; mt < 2; mt++) {
#pragma unroll
        for (int nt = 0; nt < 8; nt++) {
            const int row = rbase + mt*16;
            const int col = cbase + nt*8;
            const float b0 = bias[col], b1 = bias[col+1];
            float v0x = acc[mt][nt][0] + b0, v0y = acc[mt][nt][1] + b1;
            float v1x = acc[mt][nt][2] + b0, v1y = acc[mt][nt][3] + b1;
            if (RELU) {
                v0x = fmaxf(v0x, 0.f); v0y = fmaxf(v0y, 0.f);
                v1x = fmaxf(v1x, 0.f); v1y = fmaxf(v1y, 0.f);
            }
            if (OUT == 2) {
                *(uint32_t*)(Ch + (size_t)row*N + col)     = pack2(v0x, v0y);
                *(uint32_t*)(Ch + (size_t)(row+8)*N + col) = pack2(v1x, v1y);
            } else {
                float2 a = {v0x, v0y}, b = {v1x, v1y};
                *(float2*)(Cf + (size_t)row*N + col)     = a;
                *(float2*)(Cf + (size_t)(row+8)*N + col) = b;
            }
        }
    }
}

// ============================================================================
// fp16 HMMA flash attention, single-precision (1-term S and PV).
// Q-tile 128, 3-stage cp.async K/V pipeline.
// grid (P/128, NH, B), 256 threads = 8 warps. Output: single fp16.
// smem: Q at 0 (18432B); stage s at 18432+s*18432: K +0 (9216B), V +9216.
// ============================================================================
#define AST 72
#define KVSTG 18432u
#define ATT_SMEM_BYTES (18432 + 3*18432)   // 73728

__global__ __launch_bounds__(256)
void attn_mma(const hf* __restrict__ QKV, hf* __restrict__ Aout) {
    extern __shared__ __align__(16) char smx[];
    const uint32_t sb = smem_u32(smx);

    const int tid = threadIdx.x;
    const int lane = tid & 31;
    const int wid = tid >> 5;          // 0..7
    const int l16 = lane & 15;
    const int qt = blockIdx.x, hh = blockIdx.y, bb = blockIdx.z;
    const int nbase = bb * PSEQ;
    const int hoff  = hh * DKH;

#define KV_ISSUE(kcn) do {                                                    \
    if ((kcn) < 16) {                                                         \
        const uint32_t B = sb + 18432u + (uint32_t)((kcn) % 3) * KVSTG;       \
        _Pragma("unroll")                                                     \
        for (int it = 0; it < 2; it++) {                                      \
            int idx = tid + it*256;                                           \
            int r = idx >> 3;                                                 \
            int c8 = (idx & 7) * 8;                                           \
            const size_t go = (size_t)(nbase + (kcn)*64 + r)*(3*EMB) + hoff + c8; \
            const uint32_t o = (uint32_t)(r*144 + c8*2);                      \
            cpa16(B + o,          QKV + 512 + go);                            \
            cpa16(B + 9216u + o,  QKV + 1024 + go);                           \
        }                                                                     \
    }                                                                         \
    asm volatile("cp.async.commit_group;" ::: "memory");                      \
} while (0)

    // ---- Q tile (128x64) via cp.async; grouped with KV chunk 0 ----
#pragma unroll
    for (int it = 0; it < 4; it++) {
        int idx = tid + it*256;
        int r = idx >> 3;
        int c8 = (idx & 7) * 8;
        const size_t go = (size_t)(nbase + qt*128 + r)*(3*EMB) + hoff + c8;
        cpa16(sb + (uint32_t)(r*144 + c8*2), QKV + go);
    }
    KV_ISSUE(0);      // group0 = {Q, KV0}
    KV_ISSUE(1);      // group1 = {KV1}
    KV_ISSUE(2);      // group2 = {KV2}

    float o_acc[8][4];
#pragma unroll
    for (int i = 0; i < 8; i++)
#pragma unroll
        for (int j = 0; j < 4; j++) o_acc[i][j] = 0.f;
    float m_g = -1e30f, m_g8 = -1e30f, l_g = 0.f, l_g8 = 0.f;

    uint32_t qh[4][4];
    const uint32_t offA = (uint32_t)(((wid*16 + l16) * AST + (lane >> 4) * 8) * 2);
    const uint32_t offBr = (uint32_t)((((l16 & 7)) * AST + ((l16 >> 3)) * 8) * 2);
    const uint32_t offVt = (uint32_t)((((lane & 7) + ((lane >> 3) & 1) * 8)) * AST * 2
                                      + ((lane >> 4) * 8) * 2);

    for (int kc = 0; kc < 16; kc++) {
        asm volatile("cp.async.wait_group 2;" ::: "memory");
        __syncthreads();
        const uint32_t stB = sb + 18432u + (uint32_t)(kc % 3) * KVSTG;

        if (kc == 0) {
#pragma unroll
            for (int ks = 0; ks < 4; ks++)
                LDSM4(qh[ks], sb + offA + (uint32_t)(ks*32));
        }

        // ---- S = Q @ K^T (single term) ----
        float s[8][4];
#pragma unroll
        for (int nt = 0; nt < 8; nt++)
#pragma unroll
            for (int j = 0; j < 4; j++) s[nt][j] = 0.f;
#pragma unroll
        for (int np = 0; np < 4; np++) {
            const int n0 = 2*np, n1 = 2*np + 1;
#pragma unroll
            for (int ks = 0; ks < 4; ks++) {
                uint32_t b0[2], b1[2];
                LDSM2(b0, stB + offBr + (uint32_t)(n0*8*AST*2 + ks*32));
                LDSM2(b1, stB + offBr + (uint32_t)(n1*8*AST*2 + ks*32));
                MMA_F16(s[n0], qh[ks], b0);
                MMA_F16(s[n1], qh[ks], b1);
            }
        }
#pragma unroll
        for (int nt = 0; nt < 8; nt++) {
            s[nt][0] *= 0.125f; s[nt][1] *= 0.125f;
            s[nt][2] *= 0.125f; s[nt][3] *= 0.125f;
        }

        // ---- online softmax ----
        float cmg = -1e30f, cmg8 = -1e30f;
#pragma unroll
        for (int nt = 0; nt < 8; nt++) {
            cmg  = fmaxf(cmg,  fmaxf(s[nt][0], s[nt][1]));
            cmg8 = fmaxf(cmg8, fmaxf(s[nt][2], s[nt][3]));
        }
        cmg  = fmaxf(cmg,  __shfl_xor_sync(0xffffffffu, cmg, 1));
        cmg  = fmaxf(cmg,  __shfl_xor_sync(0xffffffffu, cmg, 2));
        cmg8 = fmaxf(cmg8, __shfl_xor_sync(0xffffffffu, cmg8, 1));
        cmg8 = fmaxf(cmg8, __shfl_xor_sync(0xffffffffu, cmg8, 2));
        const float mn  = fmaxf(m_g,  cmg);
        const float mn8 = fmaxf(m_g8, cmg8);
        const float alg  = __expf(m_g  - mn);
        const float alg8 = __expf(m_g8 - mn8);
        m_g = mn; m_g8 = mn8;
        float sum = 0.f, sum8 = 0.f;
#pragma unroll
        for (int nt = 0; nt < 8; nt++) {
            s[nt][0] = __expf(s[nt][0] - mn);
            s[nt][1] = __expf(s[nt][1] - mn);
            s[nt][2] = __expf(s[nt][2] - mn8);
            s[nt][3] = __expf(s[nt][3] - mn8);
            sum  += s[nt][0] + s[nt][1];
            sum8 += s[nt][2] + s[nt][3];
        }
        sum  += __shfl_xor_sync(0xffffffffu, sum, 1);
        sum  += __shfl_xor_sync(0xffffffffu, sum, 2);
        sum8 += __shfl_xor_sync(0xffffffffu, sum8, 1);
        sum8 += __shfl_xor_sync(0xffffffffu, sum8, 2);
        l_g  = l_g  * alg  + sum;
        l_g8 = l_g8 * alg8 + sum8;
#pragma unroll
        for (int dt = 0; dt < 8; dt++) {
            o_acc[dt][0] *= alg;  o_acc[dt][1] *= alg;
            o_acc[dt][2] *= alg8; o_acc[dt][3] *= alg8;
        }

        // ---- P fragments (single fp16) ----
        uint32_t ph[4][4];
#pragma unroll
        for (int ks = 0; ks < 4; ks++) {
            ph[ks][0] = pack2(s[2*ks][0],   s[2*ks][1]);
            ph[ks][1] = pack2(s[2*ks][2],   s[2*ks][3]);
            ph[ks][2] = pack2(s[2*ks+1][0], s[2*ks+1][1]);
            ph[ks][3] = pack2(s[2*ks+1][2], s[2*ks+1][3]);
        }

        // ---- O += P @ V (single term, trans ldmatrix) ----
#pragma unroll
        for (int dt2 = 0; dt2 < 4; dt2++) {
#pragma unroll
            for (int ks = 0; ks < 4; ks++) {
                uint32_t v4[4];
                LDSM4T(v4, stB + 9216u + offVt + (uint32_t)(ks*16*AST*2 + dt2*32));
                MMA_F16(o_acc[2*dt2],   ph[ks], v4);
                MMA_F16(o_acc[2*dt2+1], ph[ks], &v4[2]);
            }
        }
        __syncthreads();   // all reads of stage kc%3 done before refill
        KV_ISSUE(kc + 3);
    }

    // ---- epilogue: single fp16 ----
    const float ig  = 1.f / l_g;
    const float ig8 = 1.f / l_g8;
    const int g = lane >> 2;
    const int r0 = nbase + qt*128 + wid*16 + g;
    const int cb = hoff + 2*(lane & 3);
#pragma unroll
    for (int dt = 0; dt < 8; dt++) {
        *(uint32_t*)(Aout + (size_t)r0*EMB + cb + dt*8) =
            pack2(o_acc[dt][0]*ig,  o_acc[dt][1]*ig);
        *(uint32_t*)(Aout + (size_t)(r0+8)*EMB + cb + dt*8) =
            pack2(o_acc[dt][2]*ig8, o_acc[dt][3]*ig8);
    }
}

// ---------------- weight convert / pack kernels ------------------------------
__global__ void conv_w4(const float* __restrict__ src, hf* __restrict__ h,
                        int n_per_layer, int dst_stride, int dst_off) {
    int idx = blockIdx.x * blockDim.x + threadIdx.x;
    int total4 = (NLAYER * n_per_layer) >> 2;
    if (idx >= total4) return;
    int base = idx * 4;
    int layer = base / n_per_layer;
    int i = base - layer * n_per_layer;
    float4 v = *(const float4*)(src + base);
    size_t d = (size_t)layer * dst_stride + dst_off + i;
    uint2 hv = {pack2(v.x, v.y), pack2(v.z, v.w)};
    *(uint2*)(h + d) = hv;
}

__global__ void pack_bqkv(const float* __restrict__ bq, const float* __restrict__ bk,
                          const float* __restrict__ bv, float* __restrict__ dst) {
    int idx = blockIdx.x * blockDim.x + threadIdx.x;
    if (idx >= NLAYER * 3 * EMB) return;
    int l = idx / (3*EMB);
    int n = idx - l * 3*EMB;
    float v;
    if (n < EMB)            v = bq[l*EMB + n];
    else if (n < 2*EMB)     v = bk[l*EMB + n - EMB];
    else                    v = bv[l*EMB + n - 2*EMB];
    dst[idx] = v;
}

// ---------------- positional encoding table --------------------------------
__global__ void pe_kernel(float* __restrict__ pe) {
    int idx = blockIdx.x * blockDim.x + threadIdx.x;
    if (idx >= PSEQ*EMB) return;
    int p = idx >> 9;
    int e = idx & 511;
    int i2 = e >> 1;
    float c = (float)(2*i2) * (-0.017988946039015984f);
    float freqf = (float)exp((double)c);
    float angf  = (float)p * freqf;
    double angle = (double)angf;
    pe[idx] = (e & 1) ? (float)cos(angle) : (float)sin(angle);
}

// ---------------- embedding: conv + linear + PE, writes x + fp16 copy --------
__global__ void embed_kernel(const float* __restrict__ data,
                             const float* __restrict__ cw,
                             const float* __restrict__ cb,
                             const float* __restrict__ lw,
                             const float* __restrict__ lb,
                             const float* __restrict__ pe,
                             float* __restrict__ x,
                             hf* __restrict__ xh) {
    int idx = blockIdx.x * blockDim.x + threadIdx.x;
    if (idx >= NTOK*EMB) return;
    int n = idx >> 9;
    int e = idx & 511;
    int b = n >> 10;
    int p = n & 1023;
    int pi = p >> 5, pj = p & 31;
    const float* dp = data + b*4096 + (pi*2)*64 + pj*2;
    float conv = dp[0]*cw[0] + dp[1]*cw[1] + dp[64]*cw[2] + dp[65]*cw[3] + cb[0];
    float v = conv * lw[e] + lb[e] + pe[p*EMB + e];
    x[idx] = v;
    xh[idx] = __float2half_rn(v);
}

// ---------------- residual add + LayerNorm, writes x + fp16 copy -------------
__global__ __launch_bounds__(128)
void add_ln_kernel(float* __restrict__ x, const float* __restrict__ y,
                   const float* __restrict__ gam, const float* __restrict__ bet,
                   hf* __restrict__ xh) {
    const int row = blockIdx.x;
    const int tid = threadIdx.x;
    const int e = tid * 4;
    float4 xv = *(float4*)&x[(size_t)row*EMB + e];
    float4 yv = *(const float4*)&y[(size_t)row*EMB + e];
    float t0 = xv.x + yv.x, t1 = xv.y + yv.y, t2 = xv.z + yv.z, t3 = xv.w + yv.w;
    float s  = t0 + t1 + t2 + t3;
    float s2 = t0*t0 + t1*t1 + t2*t2 + t3*t3;
#pragma unroll
    for (int off = 16; off > 0; off >>= 1) {
        s  += __shfl_xor_sync(0xffffffffu, s,  off);
        s2 += __shfl_xor_sync(0xffffffffu, s2, off);
    }
    __shared__ float ws[4], ws2[4];
    int w = tid >> 5;
    if ((tid & 31) == 0) { ws[w] = s; ws2[w] = s2; }
    __syncthreads();
    float S  = ws[0] + ws[1] + ws[2] + ws[3];
    float S2 = ws2[0] + ws2[1] + ws2[2] + ws2[3];
    float mu  = S * (1.f/512.f);
    float var = S2 * (1.f/512.f) - mu*mu;
    float rs = rsqrtf(var + 1e-5f);
    float o0 = (t0 - mu)*rs*gam[e+0] + bet[e+0];
    float o1 = (t1 - mu)*rs*gam[e+1] + bet[e+1];
    float o2 = (t2 - mu)*rs*gam[e+2] + bet[e+2];
    float o3 = (t3 - mu)*rs*gam[e+3] + bet[e+3];
    float4 ov = {o0, o1, o2, o3};
    *(float4*)&x[(size_t)row*EMB + e] = ov;
    uint2 hv = {pack2(o0, o1), pack2(o2, o3)};
    *(uint2*)(xh + (size_t)row*EMB + e) = hv;
}

// ---------------- mean pool + final linear ----------------------------------
__global__ __launch_bounds__(512)
void pool_head_kernel(const float* __restrict__ x, const float* __restrict__ Wc,
                      const float* __restrict__ bc, float* __restrict__ out) {
    const int b = blockIdx.x;
    const int e = threadIdx.x;
    float s = 0.f;
    const float* xp = x + (size_t)b*PSEQ*EMB + e;
    for (int p = 0; p < PSEQ; p++) s += xp[(size_t)p*EMB];
    float pooled = s * (1.f/1024.f);
    __shared__ float red[512];
    red[e] = pooled * Wc[e];
    __syncthreads();
    for (int st = 256; st > 0; st >>= 1) {
        if (e < st) red[e] += red[e + st];
        __syncthreads();
    }
    if (e == 0) out[b] = red[0] + bc[0];
}

// ---------------- driver -----------------------------------------------------
extern "C" void kernel_launch(void* const* d_in, const int* in_sizes, int n_in,
                              void* d_out, int out_size) {
    const float* data   = (const float*)d_in[0];
    const float* conv_w = (const float*)d_in[1];
    const float* conv_b = (const float*)d_in[2];
    const float* lin_w  = (const float*)d_in[3];
    const float* lin_b  = (const float*)d_in[4];
    const float* Wq     = (const float*)d_in[5];
    const float* bq     = (const float*)d_in[6];
    const float* Wk     = (const float*)d_in[7];
    const float* bk     = (const float*)d_in[8];
    const float* Wv     = (const float*)d_in[9];
    const float* bv     = (const float*)d_in[10];
    const float* Wo     = (const float*)d_in[11];
    const float* bo     = (const float*)d_in[12];
    const float* ln1_g  = (const float*)d_in[13];
    const float* ln1_b  = (const float*)d_in[14];
    const float* ln2_g  = (const float*)d_in[15];
    const float* ln2_b  = (const float*)d_in[16];
    const float* W1     = (const float*)d_in[17];
    const float* b1     = (const float*)d_in[18];
    const float* W2     = (const float*)d_in[19];
    const float* b2     = (const float*)d_in[20];
    const float* Wc     = (const float*)d_in[21];
    const float* bc     = (const float*)d_in[22];
    float* out = (float*)d_out;

    float *px, *pt, *ppe, *pbqkv;
    hf *pxh, *pqkv, *pah, *phh;
    hf *pwqkv, *pwo, *pw1, *pw2;
    cudaGetSymbolAddress((void**)&px,  g_x);
    cudaGetSymbolAddress((void**)&pt,  g_t);
    cudaGetSymbolAddress((void**)&ppe, g_pe);
    cudaGetSymbolAddress((void**)&pxh, g_xh);
    cudaGetSymbolAddress((void**)&pqkv, g_qkv);
    cudaGetSymbolAddress((void**)&pah, g_ah);
    cudaGetSymbolAddress((void**)&phh, g_hh);
    cudaGetSymbolAddress((void**)&pwqkv, g_wqkv);
    cudaGetSymbolAddress((void**)&pwo, g_wo);
    cudaGetSymbolAddress((void**)&pw1, g_w1);
    cudaGetSymbolAddress((void**)&pw2, g_w2);
    cudaGetSymbolAddress((void**)&pbqkv, g_bqkv);

    cudaFuncSetAttribute(gemm_hf<0,0>, cudaFuncAttributeMaxDynamicSharedMemorySize, GSMEM_BYTES);
    cudaFuncSetAttribute(gemm_hf<0,2>, cudaFuncAttributeMaxDynamicSharedMemorySize, GSMEM_BYTES);
    cudaFuncSetAttribute(gemm_hf<1,2>, cudaFuncAttributeMaxDynamicSharedMemorySize, GSMEM_BYTES);
    cudaFuncSetAttribute(attn_mma, cudaFuncAttributeMaxDynamicSharedMemorySize, ATT_SMEM_BYTES);

    // ---- weight/bias packing (once per call) ----
    const int EE = EMB*EMB;          // 262144
    const int FE = FFD*EMB;          // 1048576
    conv_w4<<<(NLAYER*EE/4 + 255)/256, 256>>>(Wq, pwqkv, EE, 3*EE, 0);
    conv_w4<<<(NLAYER*EE/4 + 255)/256, 256>>>(Wk, pwqkv, EE, 3*EE, EE);
    conv_w4<<<(NLAYER*EE/4 + 255)/256, 256>>>(Wv, pwqkv, EE, 3*EE, 2*EE);
    conv_w4<<<(NLAYER*EE/4 + 255)/256, 256>>>(Wo, pwo, EE, EE, 0);
    conv_w4<<<(NLAYER*FE/4 + 255)/256, 256>>>(W1, pw1, FE, FE, 0);
    conv_w4<<<(NLAYER*FE/4 + 255)/256, 256>>>(W2, pw2, FE, FE, 0);
    pack_bqkv<<<(NLAYER*3*EMB + 255)/256, 256>>>(bq, bk, bv, pbqkv);

    pe_kernel<<<(PSEQ*EMB + 255)/256, 256>>>(ppe);
    embed_kernel<<<(NTOK*EMB + 255)/256, 256>>>(data, conv_w, conv_b, lin_w, lin_b,
                                                ppe, px, pxh);

    for (int l = 0; l < NLAYER; l++) {
        // fused QKV: [NTOK,512] @ [1536,512]^T -> single fp16 qkv
        gemm_hf<0,2><<<dim3(12,128), 256, GSMEM_BYTES>>>(
            pxh, pwqkv + (size_t)l*3*EE,
            pbqkv + l*3*EMB, nullptr, pqkv, NTOK, 3*EMB, EMB);

        attn_mma<<<dim3(PSEQ/128, NHEAD, BATCH), 256, ATT_SMEM_BYTES>>>(pqkv, pah);

        gemm_hf<0,0><<<dim3(4,128), 256, GSMEM_BYTES>>>(
            pah, pwo + (size_t)l*EE,
            bo + l*EMB, pt, nullptr, NTOK, EMB, EMB);
        add_ln_kernel<<<NTOK, 128>>>(px, pt, ln1_g + l*EMB, ln1_b + l*EMB, pxh);

        gemm_hf<1,2><<<dim3(16,128), 256, GSMEM_BYTES>>>(
            pxh, pw1 + (size_t)l*FE,
            b1 + l*FFD, nullptr, phh, NTOK, FFD, EMB);

        gemm_hf<0,0><<<dim3(4,128), 256, GSMEM_BYTES>>>(
            phh, pw2 + (size_t)l*FE,
            b2 + l*EMB, pt, nullptr, NTOK, EMB, FFD);
        add_ln_kernel<<<NTOK, 128>>>(px, pt, ln2_g + l*EMB, ln2_b + l*EMB, pxh);
    }

    pool_head_kernel<<<BATCH, 512>>>(px, Wc, bc, out);
}

// round 16
// speedup vs baseline: 2.3706x; 1.0075x over previous
#include <cuda_runtime.h>
#include <cuda_fp16.h>
#include <math.h>
#include <stdint.h>

#define BATCH   16
#define PSEQ    1024
#define NTOK    (BATCH*PSEQ)     // 16384
#define EMB     512
#define FFD     2048
#define NLAYER  4
#define NHEAD   8
#define DKH     64

typedef __half hf;

// ---------------- scratch (static device globals; no runtime alloc) ----------
__device__ float g_x [NTOK*EMB];
__device__ float g_t [NTOK*EMB];
__device__ float g_pe[PSEQ*EMB];
__device__ hf g_xh[NTOK*EMB];
__device__ hf g_qkv[NTOK*3*EMB];
__device__ hf g_ah[NTOK*EMB];
__device__ hf g_hh[NTOK*FFD];
__device__ hf g_wqkv[NLAYER*3*EMB*EMB];
__device__ hf g_wo[NLAYER*EMB*EMB];
__device__ hf g_w1[NLAYER*FFD*EMB];
__device__ hf g_w2[NLAYER*EMB*FFD];
__device__ float g_bqkv[NLAYER*3*EMB];

// ============================================================================
// helpers
// ============================================================================
static __device__ __forceinline__ uint32_t smem_u32(const void* p) {
    uint32_t a;
    asm("{ .reg .u64 t; cvta.to.shared.u64 t, %1; cvt.u32.u64 %0, t; }"
        : "=r"(a) : "l"(p));
    return a;
}
static __device__ __forceinline__ uint32_t pack2(float a, float b) {
    __half2 t = __floats2half2_rn(a, b);
    return *reinterpret_cast<uint32_t*>(&t);
}

#define MMA_F16(d, a, b) \
    asm volatile("mma.sync.aligned.m16n8k16.row.col.f32.f16.f16.f32 " \
        "{%0,%1,%2,%3}, {%4,%5,%6,%7}, {%8,%9}, {%0,%1,%2,%3};" \
        : "+f"((d)[0]), "+f"((d)[1]), "+f"((d)[2]), "+f"((d)[3]) \
        : "r"((a)[0]), "r"((a)[1]), "r"((a)[2]), "r"((a)[3]), \
          "r"((b)[0]), "r"((b)[1]))

#define LDSM4(r, addr) \
    asm volatile("ldmatrix.sync.aligned.m8n8.x4.shared.b16 {%0,%1,%2,%3}, [%4];" \
        : "=r"((r)[0]), "=r"((r)[1]), "=r"((r)[2]), "=r"((r)[3]) : "r"(addr))

#define LDSM4T(r, addr) \
    asm volatile("ldmatrix.sync.aligned.m8n8.x4.trans.shared.b16 {%0,%1,%2,%3}, [%4];" \
        : "=r"((r)[0]), "=r"((r)[1]), "=r"((r)[2]), "=r"((r)[3]) : "r"(addr))

#define LDSM2(r, addr) \
    asm volatile("ldmatrix.sync.aligned.m8n8.x2.shared.b16 {%0,%1}, [%2];" \
        : "=r"((r)[0]), "=r"((r)[1]) : "r"(addr))

static __device__ __forceinline__ void cpa16(uint32_t d, const void* s) {
    asm volatile("cp.async.cg.shared.global [%0], [%1], 16;" :: "r"(d), "l"(s));
}

// swizzled byte offset inside a 128x32-hf tile (rows of 64B = 4x16B chunks)
static __device__ __forceinline__ uint32_t swz32(int r, int c) {
    return (uint32_t)(r * 64 + ((c ^ ((r >> 1) & 3)) << 4));
}

// ============================================================================
// fp16 HMMA GEMM: C = A @ W^T + bias   (single term, fp16 A and W)
// BM=BN=128, BK=32, 2-stage cp.async, 2 CTAs/SM.
// OUT: 0 = fp32, 2 = single fp16.
// ============================================================================
#define GSTAGE 16384u
#define GSMEM_BYTES (2*GSTAGE)   // 32768

template<int RELU, int OUT>
__global__ __launch_bounds__(256, 2)
void gemm_hf(const hf* __restrict__ A, const hf* __restrict__ W,
             const float* __restrict__ bias,
             float* __restrict__ Cf, hf* __restrict__ Ch,
             int M, int N, int K) {
    extern __shared__ __align__(16) char dsm[];
    const uint32_t sb = smem_u32(dsm);
    const int tid = threadIdx.x, lane = tid & 31, wid = tid >> 5;
    const int wm = wid & 3, wn = wid >> 2;
    const int bx = blockIdx.x, by = blockIdx.y;
    const int KT = K >> 5;

    float acc[2][8][4];
#pragma unroll
    for (int i = 0; i < 2; i++)
#pragma unroll
        for (int j = 0; j < 8; j++)
#pragma unroll
            for (int q = 0; q < 4; q++) acc[i][j][q] = 0.f;

    const int cr = tid >> 2, cc = tid & 3;
    const size_t aoff = (size_t)(by*128 + cr)*K + cc*8;
    const size_t woff = (size_t)(bx*128 + cr)*K + cc*8;
    const uint32_t so0 = swz32(cr, cc), so1 = swz32(cr + 64, cc);

    const int l16 = lane & 15;
    const int rB = (lane & 7) + ((lane >> 4) << 3);
    const int cB = (lane >> 3) & 1;

#define G_ISSUE(ktn) do {                                                     \
    if ((ktn) < KT) {                                                         \
        const uint32_t stb = sb + (uint32_t)((ktn) & 1) * GSTAGE;             \
        const int ko = (ktn) * 32;                                            \
        cpa16(stb + so0,          A + aoff + ko);                             \
        cpa16(stb + so1,          A + aoff + (size_t)64*K + ko);              \
        cpa16(stb + 8192u + so0,  W + woff + ko);                             \
        cpa16(stb + 8192u + so1,  W + woff + (size_t)64*K + ko);              \
    }                                                                         \
    asm volatile("cp.async.commit_group;" ::: "memory");                      \
} while (0)

    G_ISSUE(0);

    for (int kt = 0; kt < KT; kt++) {
        G_ISSUE(kt + 1);
        asm volatile("cp.async.wait_group 1;" ::: "memory");
        __syncthreads();

        const uint32_t stb = sb + (uint32_t)(kt & 1) * GSTAGE;
#pragma unroll
        for (int ks = 0; ks < 2; ks++) {
            uint32_t ah[2][4];
            uint32_t bh[4][4];
#pragma unroll
            for (int mt = 0; mt < 2; mt++) {
                const uint32_t oa = stb + swz32(wm*32 + mt*16 + l16, ks*2 + (lane >> 4));
                LDSM4(ah[mt], oa);
            }
#pragma unroll
            for (int ntp = 0; ntp < 4; ntp++) {
                const uint32_t ob = stb + 8192u + swz32(wn*64 + ntp*16 + rB, ks*2 + cB);
                LDSM4(bh[ntp], ob);
            }
#pragma unroll
            for (int ntp = 0; ntp < 4; ntp++)
#pragma unroll
                for (int mt = 0; mt < 2; mt++) {
                    MMA_F16(acc[mt][2*ntp],   ah[mt], bh[ntp]);
                    MMA_F16(acc[mt][2*ntp+1], ah[mt], &bh[ntp][2]);
                }
        }
        __syncthreads();   // reads of buffer kt&1 done before it is re-filled
    }

    const int rbase = by*128 + wm*32 + (lane >> 2);
    const int cbase = bx*128 + wn*64 + 2*(lane & 3);
#pragma unroll
    for (int mt = 0; mt < 2; mt++) {
#pragma unroll
        for (int nt = 0; nt < 8; nt++) {
            const int row = rbase + mt*16;
            const int col = cbase + nt*8;
            const float b0 = bias[col], b1 = bias[col+1];
            float v0x = acc[mt][nt][0] + b0, v0y = acc[mt][nt][1] + b1;
            float v1x = acc[mt][nt][2] + b0, v1y = acc[mt][nt][3] + b1;
            if (RELU) {
                v0x = fmaxf(v0x, 0.f); v0y = fmaxf(v0y, 0.f);
                v1x = fmaxf(v1x, 0.f); v1y = fmaxf(v1y, 0.f);
            }
            if (OUT == 2) {
                *(uint32_t*)(Ch + (size_t)row*N + col)     = pack2(v0x, v0y);
                *(uint32_t*)(Ch + (size_t)(row+8)*N + col) = pack2(v1x, v1y);
            } else {
                float2 a = {v0x, v0y}, b = {v1x, v1y};
                *(float2*)(Cf + (size_t)row*N + col)     = a;
                *(float2*)(Cf + (size_t)(row+8)*N + col) = b;
            }
        }
    }
}

// ============================================================================
// fp16 HMMA flash attention, single-precision (1-term S and PV).
// Q-tile 128, 2-stage cp.async K/V pipeline, 2 CTAs/SM.
// grid (P/128, NH, B), 256 threads = 8 warps. Output: single fp16.
// smem: Q at 0 (18432B); stage s at 18432+s*18432: K +0 (9216B), V +9216.
// ============================================================================
#define AST 72
#define KVSTG 18432u
#define ATT_SMEM_BYTES (18432 + 2*18432)   // 55296

__global__ __launch_bounds__(256, 2)
void attn_mma(const hf* __restrict__ QKV, hf* __restrict__ Aout) {
    extern __shared__ __align__(16) char smx[];
    const uint32_t sb = smem_u32(smx);

    const int tid = threadIdx.x;
    const int lane = tid & 31;
    const int wid = tid >> 5;          // 0..7
    const int l16 = lane & 15;
    const int qt = blockIdx.x, hh = blockIdx.y, bb = blockIdx.z;
    const int nbase = bb * PSEQ;
    const int hoff  = hh * DKH;

#define KV_ISSUE(kcn) do {                                                    \
    if ((kcn) < 16) {                                                         \
        const uint32_t B = sb + 18432u + (uint32_t)((kcn) & 1) * KVSTG;       \
        _Pragma("unroll")                                                     \
        for (int it = 0; it < 2; it++) {                                      \
            int idx = tid + it*256;                                           \
            int r = idx >> 3;                                                 \
            int c8 = (idx & 7) * 8;                                           \
            const size_t go = (size_t)(nbase + (kcn)*64 + r)*(3*EMB) + hoff + c8; \
            const uint32_t o = (uint32_t)(r*144 + c8*2);                      \
            cpa16(B + o,          QKV + 512 + go);                            \
            cpa16(B + 9216u + o,  QKV + 1024 + go);                           \
        }                                                                     \
    }                                                                         \
    asm volatile("cp.async.commit_group;" ::: "memory");                      \
} while (0)

    // ---- Q tile (128x64) via cp.async; grouped with KV chunk 0 ----
#pragma unroll
    for (int it = 0; it < 4; it++) {
        int idx = tid + it*256;
        int r = idx >> 3;
        int c8 = (idx & 7) * 8;
        const size_t go = (size_t)(nbase + qt*128 + r)*(3*EMB) + hoff + c8;
        cpa16(sb + (uint32_t)(r*144 + c8*2), QKV + go);
    }
    KV_ISSUE(0);      // group0 = {Q, KV0}
    KV_ISSUE(1);      // group1 = {KV1}

    float o_acc[8][4];
#pragma unroll
    for (int i = 0; i < 8; i++)
#pragma unroll
        for (int j = 0; j < 4; j++) o_acc[i][j] = 0.f;
    float m_g = -1e30f, m_g8 = -1e30f, l_g = 0.f, l_g8 = 0.f;

    uint32_t qh[4][4];
    const uint32_t offA = (uint32_t)(((wid*16 + l16) * AST + (lane >> 4) * 8) * 2);
    const uint32_t offBr = (uint32_t)((((l16 & 7)) * AST + ((l16 >> 3)) * 8) * 2);
    const uint32_t offVt = (uint32_t)((((lane & 7) + ((lane >> 3) & 1) * 8)) * AST * 2
                                      + ((lane >> 4) * 8) * 2);

    for (int kc = 0; kc < 16; kc++) {
        asm volatile("cp.async.wait_group 1;" ::: "memory");
        __syncthreads();
        const uint32_t stB = sb + 18432u + (uint32_t)(kc & 1) * KVSTG;

        if (kc == 0) {
#pragma unroll
            for (int ks = 0; ks < 4; ks++)
                LDSM4(qh[ks], sb + offA + (uint32_t)(ks*32));
        }

        // ---- S = Q @ K^T (single term) ----
        float s[8][4];
#pragma unroll
        for (int nt = 0; nt < 8; nt++)
#pragma unroll
            for (int j = 0; j < 4; j++) s[nt][j] = 0.f;
#pragma unroll
        for (int np = 0; np < 4; np++) {
            const int n0 = 2*np, n1 = 2*np + 1;
#pragma unroll
            for (int ks = 0; ks < 4; ks++) {
                uint32_t b0[2], b1[2];
                LDSM2(b0, stB + offBr + (uint32_t)(n0*8*AST*2 + ks*32));
                LDSM2(b1, stB + offBr + (uint32_t)(n1*8*AST*2 + ks*32));
                MMA_F16(s[n0], qh[ks], b0);
                MMA_F16(s[n1], qh[ks], b1);
            }
        }
#pragma unroll
        for (int nt = 0; nt < 8; nt++) {
            s[nt][0] *= 0.125f; s[nt][1] *= 0.125f;
            s[nt][2] *= 0.125f; s[nt][3] *= 0.125f;
        }

        // ---- online softmax ----
        float cmg = -1e30f, cmg8 = -1e30f;
#pragma unroll
        for (int nt = 0; nt < 8; nt++) {
            cmg  = fmaxf(cmg,  fmaxf(s[nt][0], s[nt][1]));
            cmg8 = fmaxf(cmg8, fmaxf(s[nt][2], s[nt][3]));
        }
        cmg  = fmaxf(cmg,  __shfl_xor_sync(0xffffffffu, cmg, 1));
        cmg  = fmaxf(cmg,  __shfl_xor_sync(0xffffffffu, cmg, 2));
        cmg8 = fmaxf(cmg8, __shfl_xor_sync(0xffffffffu, cmg8, 1));
        cmg8 = fmaxf(cmg8, __shfl_xor_sync(0xffffffffu, cmg8, 2));
        const float mn  = fmaxf(m_g,  cmg);
        const float mn8 = fmaxf(m_g8, cmg8);
        const float alg  = __expf(m_g  - mn);
        const float alg8 = __expf(m_g8 - mn8);
        m_g = mn; m_g8 = mn8;
        float sum = 0.f, sum8 = 0.f;
#pragma unroll
        for (int nt = 0; nt < 8; nt++) {
            s[nt][0] = __expf(s[nt][0] - mn);
            s[nt][1] = __expf(s[nt][1] - mn);
            s[nt][2] = __expf(s[nt][2] - mn8);
            s[nt][3] = __expf(s[nt][3] - mn8);
            sum  += s[nt][0] + s[nt][1];
            sum8 += s[nt][2] + s[nt][3];
        }
        sum  += __shfl_xor_sync(0xffffffffu, sum, 1);
        sum  += __shfl_xor_sync(0xffffffffu, sum, 2);
        sum8 += __shfl_xor_sync(0xffffffffu, sum8, 1);
        sum8 += __shfl_xor_sync(0xffffffffu, sum8, 2);
        l_g  = l_g  * alg  + sum;
        l_g8 = l_g8 * alg8 + sum8;
#pragma unroll
        for (int dt = 0; dt < 8; dt++) {
            o_acc[dt][0] *= alg;  o_acc[dt][1] *= alg;
            o_acc[dt][2] *= alg8; o_acc[dt][3] *= alg8;
        }

        // ---- P fragments (single fp16) ----
        uint32_t ph[4][4];
#pragma unroll
        for (int ks = 0; ks < 4; ks++) {
            ph[ks][0] = pack2(s[2*ks][0],   s[2*ks][1]);
            ph[ks][1] = pack2(s[2*ks][2],   s[2*ks][3]);
            ph[ks][2] = pack2(s[2*ks+1][0], s[2*ks+1][1]);
            ph[ks][3] = pack2(s[2*ks+1][2], s[2*ks+1][3]);
        }

        // ---- O += P @ V (single term, trans ldmatrix) ----
#pragma unroll
        for (int dt2 = 0; dt2 < 4; dt2++) {
#pragma unroll
            for (int ks = 0; ks < 4; ks++) {
                uint32_t v4[4];
                LDSM4T(v4, stB + 9216u + offVt + (uint32_t)(ks*16*AST*2 + dt2*32));
                MMA_F16(o_acc[2*dt2],   ph[ks], v4);
                MMA_F16(o_acc[2*dt2+1], ph[ks], &v4[2]);
            }
        }
        __syncthreads();   // all reads of stage kc&1 done before refill
        KV_ISSUE(kc + 2);
    }

    // ---- epilogue: single fp16 ----
    const float ig  = 1.f / l_g;
    const float ig8 = 1.f / l_g8;
    const int g = lane >> 2;
    const int r0 = nbase + qt*128 + wid*16 + g;
    const int cb = hoff + 2*(lane & 3);
#pragma unroll
    for (int dt = 0; dt < 8; dt++) {
        *(uint32_t*)(Aout + (size_t)r0*EMB + cb + dt*8) =
            pack2(o_acc[dt][0]*ig,  o_acc[dt][1]*ig);
        *(uint32_t*)(Aout + (size_t)(r0+8)*EMB + cb + dt*8) =
            pack2(o_acc[dt][2]*ig8, o_acc[dt][3]*ig8);
    }
}

// ---------------- weight convert / pack kernels ------------------------------
__global__ void conv_w4(const float* __restrict__ src, hf* __restrict__ h,
                        int n_per_layer, int dst_stride, int dst_off) {
    int idx = blockIdx.x * blockDim.x + threadIdx.x;
    int total4 = (NLAYER * n_per_layer) >> 2;
    if (idx >= total4) return;
    int base = idx * 4;
    int layer = base / n_per_layer;
    int i = base - layer * n_per_layer;
    float4 v = *(const float4*)(src + base);
    size_t d = (size_t)layer * dst_stride + dst_off + i;
    uint2 hv = {pack2(v.x, v.y), pack2(v.z, v.w)};
    *(uint2*)(h + d) = hv;
}

__global__ void pack_bqkv(const float* __restrict__ bq, const float* __restrict__ bk,
                          const float* __restrict__ bv, float* __restrict__ dst) {
    int idx = blockIdx.x * blockDim.x + threadIdx.x;
    if (idx >= NLAYER * 3 * EMB) return;
    int l = idx / (3*EMB);
    int n = idx - l * 3*EMB;
    float v;
    if (n < EMB)            v = bq[l*EMB + n];
    else if (n < 2*EMB)     v = bk[l*EMB + n - EMB];
    else                    v = bv[l*EMB + n - 2*EMB];
    dst[idx] = v;
}

// ---------------- positional encoding table --------------------------------
__global__ void pe_kernel(float* __restrict__ pe) {
    int idx = blockIdx.x * blockDim.x + threadIdx.x;
    if (idx >= PSEQ*EMB) return;
    int p = idx >> 9;
    int e = idx & 511;
    int i2 = e >> 1;
    float c = (float)(2*i2) * (-0.017988946039015984f);
    float freqf = (float)exp((double)c);
    float angf  = (float)p * freqf;
    double angle = (double)angf;
    pe[idx] = (e & 1) ? (float)cos(angle) : (float)sin(angle);
}

// ---------------- embedding: conv + linear + PE, writes x + fp16 copy --------
__global__ void embed_kernel(const float* __restrict__ data,
                             const float* __restrict__ cw,
                             const float* __restrict__ cb,
                             const float* __restrict__ lw,
                             const float* __restrict__ lb,
                             const float* __restrict__ pe,
                             float* __restrict__ x,
                             hf* __restrict__ xh) {
    int idx = blockIdx.x * blockDim.x + threadIdx.x;
    if (idx >= NTOK*EMB) return;
    int n = idx >> 9;
    int e = idx & 511;
    int b = n >> 10;
    int p = n & 1023;
    int pi = p >> 5, pj = p & 31;
    const float* dp = data + b*4096 + (pi*2)*64 + pj*2;
    float conv = dp[0]*cw[0] + dp[1]*cw[1] + dp[64]*cw[2] + dp[65]*cw[3] + cb[0];
    float v = conv * lw[e] + lb[e] + pe[p*EMB + e];
    x[idx] = v;
    xh[idx] = __float2half_rn(v);
}

// ---------------- residual add + LayerNorm, writes x + fp16 copy -------------
__global__ __launch_bounds__(128)
void add_ln_kernel(float* __restrict__ x, const float* __restrict__ y,
                   const float* __restrict__ gam, const float* __restrict__ bet,
                   hf* __restrict__ xh) {
    const int row = blockIdx.x;
    const int tid = threadIdx.x;
    const int e = tid * 4;
    float4 xv = *(float4*)&x[(size_t)row*EMB + e];
    float4 yv = *(const float4*)&y[(size_t)row*EMB + e];
    float t0 = xv.x + yv.x, t1 = xv.y + yv.y, t2 = xv.z + yv.z, t3 = xv.w + yv.w;
    float s  = t0 + t1 + t2 + t3;
    float s2 = t0*t0 + t1*t1 + t2*t2 + t3*t3;
#pragma unroll
    for (int off = 16; off > 0; off >>= 1) {
        s  += __shfl_xor_sync(0xffffffffu, s,  off);
        s2 += __shfl_xor_sync(0xffffffffu, s2, off);
    }
    __shared__ float ws[4], ws2[4];
    int w = tid >> 5;
    if ((tid & 31) == 0) { ws[w] = s; ws2[w] = s2; }
    __syncthreads();
    float S  = ws[0] + ws[1] + ws[2] + ws[3];
    float S2 = ws2[0] + ws2[1] + ws2[2] + ws2[3];
    float mu  = S * (1.f/512.f);
    float var = S2 * (1.f/512.f) - mu*mu;
    float rs = rsqrtf(var + 1e-5f);
    float o0 = (t0 - mu)*rs*gam[e+0] + bet[e+0];
    float o1 = (t1 - mu)*rs*gam[e+1] + bet[e+1];
    float o2 = (t2 - mu)*rs*gam[e+2] + bet[e+2];
    float o3 = (t3 - mu)*rs*gam[e+3] + bet[e+3];
    float4 ov = {o0, o1, o2, o3};
    *(float4*)&x[(size_t)row*EMB + e] = ov;
    uint2 hv = {pack2(o0, o1), pack2(o2, o3)};
    *(uint2*)(xh + (size_t)row*EMB + e) = hv;
}

// ---------------- mean pool + final linear ----------------------------------
__global__ __launch_bounds__(512)
void pool_head_kernel(const float* __restrict__ x, const float* __restrict__ Wc,
                      const float* __restrict__ bc, float* __restrict__ out) {
    const int b = blockIdx.x;
    const int e = threadIdx.x;
    float s = 0.f;
    const float* xp = x + (size_t)b*PSEQ*EMB + e;
    for (int p = 0; p < PSEQ; p++) s += xp[(size_t)p*EMB];
    float pooled = s * (1.f/1024.f);
    __shared__ float red[512];
    red[e] = pooled * Wc[e];
    __syncthreads();
    for (int st = 256; st > 0; st >>= 1) {
        if (e < st) red[e] += red[e + st];
        __syncthreads();
    }
    if (e == 0) out[b] = red[0] + bc[0];
}

// ---------------- driver -----------------------------------------------------
extern "C" void kernel_launch(void* const* d_in, const int* in_sizes, int n_in,
                              void* d_out, int out_size) {
    const float* data   = (const float*)d_in[0];
    const float* conv_w = (const float*)d_in[1];
    const float* conv_b = (const float*)d_in[2];
    const float* lin_w  = (const float*)d_in[3];
    const float* lin_b  = (const float*)d_in[4];
    const float* Wq     = (const float*)d_in[5];
    const float* bq     = (const float*)d_in[6];
    const float* Wk     = (const float*)d_in[7];
    const float* bk     = (const float*)d_in[8];
    const float* Wv     = (const float*)d_in[9];
    const float* bv     = (const float*)d_in[10];
    const float* Wo     = (const float*)d_in[11];
    const float* bo     = (const float*)d_in[12];
    const float* ln1_g  = (const float*)d_in[13];
    const float* ln1_b  = (const float*)d_in[14];
    const float* ln2_g  = (const float*)d_in[15];
    const float* ln2_b  = (const float*)d_in[16];
    const float* W1     = (const float*)d_in[17];
    const float* b1     = (const float*)d_in[18];
    const float* W2     = (const float*)d_in[19];
    const float* b2     = (const float*)d_in[20];
    const float* Wc     = (const float*)d_in[21];
    const float* bc     = (const float*)d_in[22];
    float* out = (float*)d_out;

    float *px, *pt, *ppe, *pbqkv;
    hf *pxh, *pqkv, *pah, *phh;
    hf *pwqkv, *pwo, *pw1, *pw2;
    cudaGetSymbolAddress((void**)&px,  g_x);
    cudaGetSymbolAddress((void**)&pt,  g_t);
    cudaGetSymbolAddress((void**)&ppe, g_pe);
    cudaGetSymbolAddress((void**)&pxh, g_xh);
    cudaGetSymbolAddress((void**)&pqkv, g_qkv);
    cudaGetSymbolAddress((void**)&pah, g_ah);
    cudaGetSymbolAddress((void**)&phh, g_hh);
    cudaGetSymbolAddress((void**)&pwqkv, g_wqkv);
    cudaGetSymbolAddress((void**)&pwo, g_wo);
    cudaGetSymbolAddress((void**)&pw1, g_w1);
    cudaGetSymbolAddress((void**)&pw2, g_w2);
    cudaGetSymbolAddress((void**)&pbqkv, g_bqkv);

    cudaFuncSetAttribute(gemm_hf<0,0>, cudaFuncAttributeMaxDynamicSharedMemorySize, GSMEM_BYTES);
    cudaFuncSetAttribute(gemm_hf<0,2>, cudaFuncAttributeMaxDynamicSharedMemorySize, GSMEM_BYTES);
    cudaFuncSetAttribute(gemm_hf<1,2>, cudaFuncAttributeMaxDynamicSharedMemorySize, GSMEM_BYTES);
    cudaFuncSetAttribute(attn_mma, cudaFuncAttributeMaxDynamicSharedMemorySize, ATT_SMEM_BYTES);

    // ---- weight/bias packing (once per call) ----
    const int EE = EMB*EMB;          // 262144
    const int FE = FFD*EMB;          // 1048576
    conv_w4<<<(NLAYER*EE/4 + 255)/256, 256>>>(Wq, pwqkv, EE, 3*EE, 0);
    conv_w4<<<(NLAYER*EE/4 + 255)/256, 256>>>(Wk, pwqkv, EE, 3*EE, EE);
    conv_w4<<<(NLAYER*EE/4 + 255)/256, 256>>>(Wv, pwqkv, EE, 3*EE, 2*EE);
    conv_w4<<<(NLAYER*EE/4 + 255)/256, 256>>>(Wo, pwo, EE, EE, 0);
    conv_w4<<<(NLAYER*FE/4 + 255)/256, 256>>>(W1, pw1, FE, FE, 0);
    conv_w4<<<(NLAYER*FE/4 + 255)/256, 256>>>(W2, pw2, FE, FE, 0);
    pack_bqkv<<<(NLAYER*3*EMB + 255)/256, 256>>>(bq, bk, bv, pbqkv);

    pe_kernel<<<(PSEQ*EMB + 255)/256, 256>>>(ppe);
    embed_kernel<<<(NTOK*EMB + 255)/256, 256>>>(data, conv_w, conv_b, lin_w, lin_b,
                                                ppe, px, pxh);

    for (int l = 0; l < NLAYER; l++) {
        // fused QKV: [NTOK,512] @ [1536,512]^T -> single fp16 qkv
        gemm_hf<0,2><<<dim3(12,128), 256, GSMEM_BYTES>>>(
            pxh, pwqkv + (size_t)l*3*EE,
            pbqkv + l*3*EMB, nullptr, pqkv, NTOK, 3*EMB, EMB);

        attn_mma<<<dim3(PSEQ/128, NHEAD, BATCH), 256, ATT_SMEM_BYTES>>>(pqkv, pah);

        gemm_hf<0,0><<<dim3(4,128), 256, GSMEM_BYTES>>>(
            pah, pwo + (size_t)l*EE,
            bo + l*EMB, pt, nullptr, NTOK, EMB, EMB);
        add_ln_kernel<<<NTOK, 128>>>(px, pt, ln1_g + l*EMB, ln1_b + l*EMB, pxh);

        gemm_hf<1,2><<<dim3(16,128), 256, GSMEM_BYTES>>>(
            pxh, pw1 + (size_t)l*FE,
            b1 + l*FFD, nullptr, phh, NTOK, FFD, EMB);

        gemm_hf<0,0><<<dim3(4,128), 256, GSMEM_BYTES>>>(
            phh, pw2 + (size_t)l*FE,
            b2 + l*EMB, pt, nullptr, NTOK, EMB, FFD);
        add_ln_kernel<<<NTOK, 128>>>(px, pt, ln2_g + l*EMB, ln2_b + l*EMB, pxh);
    }

    pool_head_kernel<<<BATCH, 512>>>(px, Wc, bc, out);
}

// round 17
// speedup vs baseline: 2.4444x; 1.0311x over previous
#include <cuda_runtime.h>
#include <cuda_fp16.h>
#include <math.h>
#include <stdint.h>

#define BATCH   16
#define PSEQ    1024
#define NTOK    (BATCH*PSEQ)     // 16384
#define EMB     512
#define FFD     2048
#define NLAYER  4
#define NHEAD   8
#define DKH     64

typedef __half hf;

// ---------------- scratch (static device globals; no runtime alloc) ----------
__device__ float g_pe[PSEQ*EMB];
__device__ hf g_xh[NTOK*EMB];        // residual stream (fp16)
__device__ hf g_th[NTOK*EMB];        // block output temp (fp16)
__device__ hf g_qkv[NTOK*3*EMB];
__device__ hf g_ah[NTOK*EMB];
__device__ hf g_hh[NTOK*FFD];
__device__ hf g_wqkv[NLAYER*3*EMB*EMB];
__device__ hf g_wo[NLAYER*EMB*EMB];
__device__ hf g_w1[NLAYER*FFD*EMB];
__device__ hf g_w2[NLAYER*EMB*FFD];
__device__ float g_bqkv[NLAYER*3*EMB];

// ============================================================================
// helpers
// ============================================================================
static __device__ __forceinline__ uint32_t smem_u32(const void* p) {
    uint32_t a;
    asm("{ .reg .u64 t; cvta.to.shared.u64 t, %1; cvt.u32.u64 %0, t; }"
        : "=r"(a) : "l"(p));
    return a;
}
static __device__ __forceinline__ uint32_t pack2(float a, float b) {
    __half2 t = __floats2half2_rn(a, b);
    return *reinterpret_cast<uint32_t*>(&t);
}

#define MMA_F16(d, a, b) \
    asm volatile("mma.sync.aligned.m16n8k16.row.col.f32.f16.f16.f32 " \
        "{%0,%1,%2,%3}, {%4,%5,%6,%7}, {%8,%9}, {%0,%1,%2,%3};" \
        : "+f"((d)[0]), "+f"((d)[1]), "+f"((d)[2]), "+f"((d)[3]) \
        : "r"((a)[0]), "r"((a)[1]), "r"((a)[2]), "r"((a)[3]), \
          "r"((b)[0]), "r"((b)[1]))

#define LDSM4(r, addr) \
    asm volatile("ldmatrix.sync.aligned.m8n8.x4.shared.b16 {%0,%1,%2,%3}, [%4];" \
        : "=r"((r)[0]), "=r"((r)[1]), "=r"((r)[2]), "=r"((r)[3]) : "r"(addr))

#define LDSM4T(r, addr) \
    asm volatile("ldmatrix.sync.aligned.m8n8.x4.trans.shared.b16 {%0,%1,%2,%3}, [%4];" \
        : "=r"((r)[0]), "=r"((r)[1]), "=r"((r)[2]), "=r"((r)[3]) : "r"(addr))

#define LDSM2(r, addr) \
    asm volatile("ldmatrix.sync.aligned.m8n8.x2.shared.b16 {%0,%1}, [%2];" \
        : "=r"((r)[0]), "=r"((r)[1]) : "r"(addr))

static __device__ __forceinline__ void cpa16(uint32_t d, const void* s) {
    asm volatile("cp.async.cg.shared.global [%0], [%1], 16;" :: "r"(d), "l"(s));
}

// swizzled byte offset inside a 128x32-hf tile (rows of 64B = 4x16B chunks)
static __device__ __forceinline__ uint32_t swz32(int r, int c) {
    return (uint32_t)(r * 64 + ((c ^ ((r >> 1) & 3)) << 4));
}

// ============================================================================
// fp16 HMMA GEMM: C = A @ W^T + bias   (single term, fp16 A and W)
// BM=BN=128, BK=32, 2-stage cp.async, 2 CTAs/SM. Output: single fp16.
// ============================================================================
#define GSTAGE 16384u
#define GSMEM_BYTES (2*GSTAGE)   // 32768

template<int RELU>
__global__ __launch_bounds__(256, 2)
void gemm_hf(const hf* __restrict__ A, const hf* __restrict__ W,
             const float* __restrict__ bias, hf* __restrict__ Ch,
             int M, int N, int K) {
    extern __shared__ __align__(16) char dsm[];
    const uint32_t sb = smem_u32(dsm);
    const int tid = threadIdx.x, lane = tid & 31, wid = tid >> 5;
    const int wm = wid & 3, wn = wid >> 2;
    const int bx = blockIdx.x, by = blockIdx.y;
    const int KT = K >> 5;

    float acc[2][8][4];
#pragma unroll
    for (int i = 0; i < 2; i++)
#pragma unroll
        for (int j = 0; j < 8; j++)
#pragma unroll
            for (int q = 0; q < 4; q++) acc[i][j][q] = 0.f;

    const int cr = tid >> 2, cc = tid & 3;
    const size_t aoff = (size_t)(by*128 + cr)*K + cc*8;
    const size_t woff = (size_t)(bx*128 + cr)*K + cc*8;
    const uint32_t so0 = swz32(cr, cc), so1 = swz32(cr + 64, cc);

    const int l16 = lane & 15;
    const int rB = (lane & 7) + ((lane >> 4) << 3);
    const int cB = (lane >> 3) & 1;

#define G_ISSUE(ktn) do {                                                     \
    if ((ktn) < KT) {                                                         \
        const uint32_t stb = sb + (uint32_t)((ktn) & 1) * GSTAGE;             \
        const int ko = (ktn) * 32;                                            \
        cpa16(stb + so0,          A + aoff + ko);                             \
        cpa16(stb + so1,          A + aoff + (size_t)64*K + ko);              \
        cpa16(stb + 8192u + so0,  W + woff + ko);                             \
        cpa16(stb + 8192u + so1,  W + woff + (size_t)64*K + ko);              \
    }                                                                         \
    asm volatile("cp.async.commit_group;" ::: "memory");                      \
} while (0)

    G_ISSUE(0);

    for (int kt = 0; kt < KT; kt++) {
        G_ISSUE(kt + 1);
        asm volatile("cp.async.wait_group 1;" ::: "memory");
        __syncthreads();

        const uint32_t stb = sb + (uint32_t)(kt & 1) * GSTAGE;
#pragma unroll
        for (int ks = 0; ks < 2; ks++) {
            uint32_t ah[2][4];
            uint32_t bh[4][4];
#pragma unroll
            for (int mt = 0; mt < 2; mt++) {
                const uint32_t oa = stb + swz32(wm*32 + mt*16 + l16, ks*2 + (lane >> 4));
                LDSM4(ah[mt], oa);
            }
#pragma unroll
            for (int ntp = 0; ntp < 4; ntp++) {
                const uint32_t ob = stb + 8192u + swz32(wn*64 + ntp*16 + rB, ks*2 + cB);
                LDSM4(bh[ntp], ob);
            }
#pragma unroll
            for (int ntp = 0; ntp < 4; ntp++)
#pragma unroll
                for (int mt = 0; mt < 2; mt++) {
                    MMA_F16(acc[mt][2*ntp],   ah[mt], bh[ntp]);
                    MMA_F16(acc[mt][2*ntp+1], ah[mt], &bh[ntp][2]);
                }
        }
        __syncthreads();   // reads of buffer kt&1 done before it is re-filled
    }

    const int rbase = by*128 + wm*32 + (lane >> 2);
    const int cbase = bx*128 + wn*64 + 2*(lane & 3);
#pragma unroll
    for (int mt = 0; mt < 2; mt++) {
#pragma unroll
        for (int nt = 0; nt < 8; nt++) {
            const int row = rbase + mt*16;
            const int col = cbase + nt*8;
            const float b0 = bias[col], b1 = bias[col+1];
            float v0x = acc[mt][nt][0] + b0, v0y = acc[mt][nt][1] + b1;
            float v1x = acc[mt][nt][2] + b0, v1y = acc[mt][nt][3] + b1;
            if (RELU) {
                v0x = fmaxf(v0x, 0.f); v0y = fmaxf(v0y, 0.f);
                v1x = fmaxf(v1x, 0.f); v1y = fmaxf(v1y, 0.f);
            }
            *(uint32_t*)(Ch + (size_t)row*N + col)     = pack2(v0x, v0y);
            *(uint32_t*)(Ch + (size_t)(row+8)*N + col) = pack2(v1x, v1y);
        }
    }
}

// ============================================================================
// fp16 HMMA flash attention, single-precision (1-term S and PV).
// Q-tile 128, 2-stage cp.async K/V pipeline, 2 CTAs/SM.
// grid (P/128, NH, B), 256 threads = 8 warps. Output: single fp16.
// ============================================================================
#define AST 72
#define KVSTG 18432u
#define ATT_SMEM_BYTES (18432 + 2*18432)   // 55296

__global__ __launch_bounds__(256, 2)
void attn_mma(const hf* __restrict__ QKV, hf* __restrict__ Aout) {
    extern __shared__ __align__(16) char smx[];
    const uint32_t sb = smem_u32(smx);

    const int tid = threadIdx.x;
    const int lane = tid & 31;
    const int wid = tid >> 5;          // 0..7
    const int l16 = lane & 15;
    const int qt = blockIdx.x, hh = blockIdx.y, bb = blockIdx.z;
    const int nbase = bb * PSEQ;
    const int hoff  = hh * DKH;

#define KV_ISSUE(kcn) do {                                                    \
    if ((kcn) < 16) {                                                         \
        const uint32_t B = sb + 18432u + (uint32_t)((kcn) & 1) * KVSTG;       \
        _Pragma("unroll")                                                     \
        for (int it = 0; it < 2; it++) {                                      \
            int idx = tid + it*256;                                           \
            int r = idx >> 3;                                                 \
            int c8 = (idx & 7) * 8;                                           \
            const size_t go = (size_t)(nbase + (kcn)*64 + r)*(3*EMB) + hoff + c8; \
            const uint32_t o = (uint32_t)(r*144 + c8*2);                      \
            cpa16(B + o,          QKV + 512 + go);                            \
            cpa16(B + 9216u + o,  QKV + 1024 + go);                           \
        }                                                                     \
    }                                                                         \
    asm volatile("cp.async.commit_group;" ::: "memory");                      \
} while (0)

    // ---- Q tile (128x64) via cp.async; grouped with KV chunk 0 ----
#pragma unroll
    for (int it = 0; it < 4; it++) {
        int idx = tid + it*256;
        int r = idx >> 3;
        int c8 = (idx & 7) * 8;
        const size_t go = (size_t)(nbase + qt*128 + r)*(3*EMB) + hoff + c8;
        cpa16(sb + (uint32_t)(r*144 + c8*2), QKV + go);
    }
    KV_ISSUE(0);
    KV_ISSUE(1);

    float o_acc[8][4];
#pragma unroll
    for (int i = 0; i < 8; i++)
#pragma unroll
        for (int j = 0; j < 4; j++) o_acc[i][j] = 0.f;
    float m_g = -1e30f, m_g8 = -1e30f, l_g = 0.f, l_g8 = 0.f;

    uint32_t qh[4][4];
    const uint32_t offA = (uint32_t)(((wid*16 + l16) * AST + (lane >> 4) * 8) * 2);
    const uint32_t offBr = (uint32_t)((((l16 & 7)) * AST + ((l16 >> 3)) * 8) * 2);
    const uint32_t offVt = (uint32_t)((((lane & 7) + ((lane >> 3) & 1) * 8)) * AST * 2
                                      + ((lane >> 4) * 8) * 2);

    for (int kc = 0; kc < 16; kc++) {
        asm volatile("cp.async.wait_group 1;" ::: "memory");
        __syncthreads();
        const uint32_t stB = sb + 18432u + (uint32_t)(kc & 1) * KVSTG;

        if (kc == 0) {
#pragma unroll
            for (int ks = 0; ks < 4; ks++)
                LDSM4(qh[ks], sb + offA + (uint32_t)(ks*32));
        }

        // ---- S = Q @ K^T ----
        float s[8][4];
#pragma unroll
        for (int nt = 0; nt < 8; nt++)
#pragma unroll
            for (int j = 0; j < 4; j++) s[nt][j] = 0.f;
#pragma unroll
        for (int np = 0; np < 4; np++) {
            const int n0 = 2*np, n1 = 2*np + 1;
#pragma unroll
            for (int ks = 0; ks < 4; ks++) {
                uint32_t b0[2], b1[2];
                LDSM2(b0, stB + offBr + (uint32_t)(n0*8*AST*2 + ks*32));
                LDSM2(b1, stB + offBr + (uint32_t)(n1*8*AST*2 + ks*32));
                MMA_F16(s[n0], qh[ks], b0);
                MMA_F16(s[n1], qh[ks], b1);
            }
        }
#pragma unroll
        for (int nt = 0; nt < 8; nt++) {
            s[nt][0] *= 0.125f; s[nt][1] *= 0.125f;
            s[nt][2] *= 0.125f; s[nt][3] *= 0.125f;
        }

        // ---- online softmax ----
        float cmg = -1e30f, cmg8 = -1e30f;
#pragma unroll
        for (int nt = 0; nt < 8; nt++) {
            cmg  = fmaxf(cmg,  fmaxf(s[nt][0], s[nt][1]));
            cmg8 = fmaxf(cmg8, fmaxf(s[nt][2], s[nt][3]));
        }
        cmg  = fmaxf(cmg,  __shfl_xor_sync(0xffffffffu, cmg, 1));
        cmg  = fmaxf(cmg,  __shfl_xor_sync(0xffffffffu, cmg, 2));
        cmg8 = fmaxf(cmg8, __shfl_xor_sync(0xffffffffu, cmg8, 1));
        cmg8 = fmaxf(cmg8, __shfl_xor_sync(0xffffffffu, cmg8, 2));
        const float mn  = fmaxf(m_g,  cmg);
        const float mn8 = fmaxf(m_g8, cmg8);
        const float alg  = __expf(m_g  - mn);
        const float alg8 = __expf(m_g8 - mn8);
        m_g = mn; m_g8 = mn8;
        float sum = 0.f, sum8 = 0.f;
#pragma unroll
        for (int nt = 0; nt < 8; nt++) {
            s[nt][0] = __expf(s[nt][0] - mn);
            s[nt][1] = __expf(s[nt][1] - mn);
            s[nt][2] = __expf(s[nt][2] - mn8);
            s[nt][3] = __expf(s[nt][3] - mn8);
            sum  += s[nt][0] + s[nt][1];
            sum8 += s[nt][2] + s[nt][3];
        }
        sum  += __shfl_xor_sync(0xffffffffu, sum, 1);
        sum  += __shfl_xor_sync(0xffffffffu, sum, 2);
        sum8 += __shfl_xor_sync(0xffffffffu, sum8, 1);
        sum8 += __shfl_xor_sync(0xffffffffu, sum8, 2);
        l_g  = l_g  * alg  + sum;
        l_g8 = l_g8 * alg8 + sum8;
#pragma unroll
        for (int dt = 0; dt < 8; dt++) {
            o_acc[dt][0] *= alg;  o_acc[dt][1] *= alg;
            o_acc[dt][2] *= alg8; o_acc[dt][3] *= alg8;
        }

        // ---- P fragments ----
        uint32_t ph[4][4];
#pragma unroll
        for (int ks = 0; ks < 4; ks++) {
            ph[ks][0] = pack2(s[2*ks][0],   s[2*ks][1]);
            ph[ks][1] = pack2(s[2*ks][2],   s[2*ks][3]);
            ph[ks][2] = pack2(s[2*ks+1][0], s[2*ks+1][1]);
            ph[ks][3] = pack2(s[2*ks+1][2], s[2*ks+1][3]);
        }

        // ---- O += P @ V ----
#pragma unroll
        for (int dt2 = 0; dt2 < 4; dt2++) {
#pragma unroll
            for (int ks = 0; ks < 4; ks++) {
                uint32_t v4[4];
                LDSM4T(v4, stB + 9216u + offVt + (uint32_t)(ks*16*AST*2 + dt2*32));
                MMA_F16(o_acc[2*dt2],   ph[ks], v4);
                MMA_F16(o_acc[2*dt2+1], ph[ks], &v4[2]);
            }
        }
        __syncthreads();
        KV_ISSUE(kc + 2);
    }

    // ---- epilogue: single fp16 ----
    const float ig  = 1.f / l_g;
    const float ig8 = 1.f / l_g8;
    const int g = lane >> 2;
    const int r0 = nbase + qt*128 + wid*16 + g;
    const int cb = hoff + 2*(lane & 3);
#pragma unroll
    for (int dt = 0; dt < 8; dt++) {
        *(uint32_t*)(Aout + (size_t)r0*EMB + cb + dt*8) =
            pack2(o_acc[dt][0]*ig,  o_acc[dt][1]*ig);
        *(uint32_t*)(Aout + (size_t)(r0+8)*EMB + cb + dt*8) =
            pack2(o_acc[dt][2]*ig8, o_acc[dt][3]*ig8);
    }
}

// ---------------- weight convert / pack kernels ------------------------------
__global__ void conv_w4(const float* __restrict__ src, hf* __restrict__ h,
                        int n_per_layer, int dst_stride, int dst_off) {
    int idx = blockIdx.x * blockDim.x + threadIdx.x;
    int total4 = (NLAYER * n_per_layer) >> 2;
    if (idx >= total4) return;
    int base = idx * 4;
    int layer = base / n_per_layer;
    int i = base - layer * n_per_layer;
    float4 v = *(const float4*)(src + base);
    size_t d = (size_t)layer * dst_stride + dst_off + i;
    uint2 hv = {pack2(v.x, v.y), pack2(v.z, v.w)};
    *(uint2*)(h + d) = hv;
}

__global__ void pack_bqkv(const float* __restrict__ bq, const float* __restrict__ bk,
                          const float* __restrict__ bv, float* __restrict__ dst) {
    int idx = blockIdx.x * blockDim.x + threadIdx.x;
    if (idx >= NLAYER * 3 * EMB) return;
    int l = idx / (3*EMB);
    int n = idx - l * 3*EMB;
    float v;
    if (n < EMB)            v = bq[l*EMB + n];
    else if (n < 2*EMB)     v = bk[l*EMB + n - EMB];
    else                    v = bv[l*EMB + n - 2*EMB];
    dst[idx] = v;
}

// ---------------- positional encoding table --------------------------------
__global__ void pe_kernel(float* __restrict__ pe) {
    int idx = blockIdx.x * blockDim.x + threadIdx.x;
    if (idx >= PSEQ*EMB) return;
    int p = idx >> 9;
    int e = idx & 511;
    int i2 = e >> 1;
    float c = (float)(2*i2) * (-0.017988946039015984f);
    float freqf = (float)exp((double)c);
    float angf  = (float)p * freqf;
    double angle = (double)angf;
    pe[idx] = (e & 1) ? (float)cos(angle) : (float)sin(angle);
}

// ---------------- embedding: conv + linear + PE -> fp16 xh -------------------
__global__ void embed_kernel(const float* __restrict__ data,
                             const float* __restrict__ cw,
                             const float* __restrict__ cb,
                             const float* __restrict__ lw,
                             const float* __restrict__ lb,
                             const float* __restrict__ pe,
                             hf* __restrict__ xh) {
    int idx = blockIdx.x * blockDim.x + threadIdx.x;
    if (idx >= NTOK*EMB) return;
    int n = idx >> 9;
    int e = idx & 511;
    int b = n >> 10;
    int p = n & 1023;
    int pi = p >> 5, pj = p & 31;
    const float* dp = data + b*4096 + (pi*2)*64 + pj*2;
    float conv = dp[0]*cw[0] + dp[1]*cw[1] + dp[64]*cw[2] + dp[65]*cw[3] + cb[0];
    float v = conv * lw[e] + lb[e] + pe[p*EMB + e];
    xh[idx] = __float2half_rn(v);
}

// ---------------- residual add + LayerNorm (fp16 in/out, fp32 math) ----------
__global__ __launch_bounds__(128)
void add_ln_kernel(hf* __restrict__ xh, const hf* __restrict__ y,
                   const float* __restrict__ gam, const float* __restrict__ bet) {
    const int row = blockIdx.x;
    const int tid = threadIdx.x;
    const int e = tid * 4;
    uint2 xu = *(uint2*)(xh + (size_t)row*EMB + e);
    uint2 yu = *(const uint2*)(y + (size_t)row*EMB + e);
    __half2 x01 = *reinterpret_cast<__half2*>(&xu.x);
    __half2 x23 = *reinterpret_cast<__half2*>(&xu.y);
    __half2 y01 = *reinterpret_cast<__half2*>(&yu.x);
    __half2 y23 = *reinterpret_cast<__half2*>(&yu.y);
    float t0 = __half2float(__low2half(x01))  + __half2float(__low2half(y01));
    float t1 = __half2float(__high2half(x01)) + __half2float(__high2half(y01));
    float t2 = __half2float(__low2half(x23))  + __half2float(__low2half(y23));
    float t3 = __half2float(__high2half(x23)) + __half2float(__high2half(y23));
    float s  = t0 + t1 + t2 + t3;
    float s2 = t0*t0 + t1*t1 + t2*t2 + t3*t3;
#pragma unroll
    for (int off = 16; off > 0; off >>= 1) {
        s  += __shfl_xor_sync(0xffffffffu, s,  off);
        s2 += __shfl_xor_sync(0xffffffffu, s2, off);
    }
    __shared__ float ws[4], ws2[4];
    int w = tid >> 5;
    if ((tid & 31) == 0) { ws[w] = s; ws2[w] = s2; }
    __syncthreads();
    float S  = ws[0] + ws[1] + ws[2] + ws[3];
    float S2 = ws2[0] + ws2[1] + ws2[2] + ws2[3];
    float mu  = S * (1.f/512.f);
    float var = S2 * (1.f/512.f) - mu*mu;
    float rs = rsqrtf(var + 1e-5f);
    float o0 = (t0 - mu)*rs*gam[e+0] + bet[e+0];
    float o1 = (t1 - mu)*rs*gam[e+1] + bet[e+1];
    float o2 = (t2 - mu)*rs*gam[e+2] + bet[e+2];
    float o3 = (t3 - mu)*rs*gam[e+3] + bet[e+3];
    uint2 hv = {pack2(o0, o1), pack2(o2, o3)};
    *(uint2*)(xh + (size_t)row*EMB + e) = hv;
}

// ---------------- mean pool + final linear (fp16 input, fp32 math) -----------
__global__ __launch_bounds__(512)
void pool_head_kernel(const hf* __restrict__ x, const float* __restrict__ Wc,
                      const float* __restrict__ bc, float* __restrict__ out) {
    const int b = blockIdx.x;
    const int e = threadIdx.x;
    float s = 0.f;
    const hf* xp = x + (size_t)b*PSEQ*EMB + e;
    for (int p = 0; p < PSEQ; p++) s += __half2float(xp[(size_t)p*EMB]);
    float pooled = s * (1.f/1024.f);
    __shared__ float red[512];
    red[e] = pooled * Wc[e];
    __syncthreads();
    for (int st = 256; st > 0; st >>= 1) {
        if (e < st) red[e] += red[e + st];
        __syncthreads();
    }
    if (e == 0) out[b] = red[0] + bc[0];
}

// ---------------- driver -----------------------------------------------------
extern "C" void kernel_launch(void* const* d_in, const int* in_sizes, int n_in,
                              void* d_out, int out_size) {
    const float* data   = (const float*)d_in[0];
    const float* conv_w = (const float*)d_in[1];
    const float* conv_b = (const float*)d_in[2];
    const float* lin_w  = (const float*)d_in[3];
    const float* lin_b  = (const float*)d_in[4];
    const float* Wq     = (const float*)d_in[5];
    const float* bq     = (const float*)d_in[6];
    const float* Wk     = (const float*)d_in[7];
    const float* bk     = (const float*)d_in[8];
    const float* Wv     = (const float*)d_in[9];
    const float* bv     = (const float*)d_in[10];
    const float* Wo     = (const float*)d_in[11];
    const float* bo     = (const float*)d_in[12];
    const float* ln1_g  = (const float*)d_in[13];
    const float* ln1_b  = (const float*)d_in[14];
    const float* ln2_g  = (const float*)d_in[15];
    const float* ln2_b  = (const float*)d_in[16];
    const float* W1     = (const float*)d_in[17];
    const float* b1     = (const float*)d_in[18];
    const float* W2     = (const float*)d_in[19];
    const float* b2     = (const float*)d_in[20];
    const float* Wc     = (const float*)d_in[21];
    const float* bc     = (const float*)d_in[22];
    float* out = (float*)d_out;

    float *ppe, *pbqkv;
    hf *pxh, *pth, *pqkv, *pah, *phh;
    hf *pwqkv, *pwo, *pw1, *pw2;
    cudaGetSymbolAddress((void**)&ppe, g_pe);
    cudaGetSymbolAddress((void**)&pxh, g_xh);
    cudaGetSymbolAddress((void**)&pth, g_th);
    cudaGetSymbolAddress((void**)&pqkv, g_qkv);
    cudaGetSymbolAddress((void**)&pah, g_ah);
    cudaGetSymbolAddress((void**)&phh, g_hh);
    cudaGetSymbolAddress((void**)&pwqkv, g_wqkv);
    cudaGetSymbolAddress((void**)&pwo, g_wo);
    cudaGetSymbolAddress((void**)&pw1, g_w1);
    cudaGetSymbolAddress((void**)&pw2, g_w2);
    cudaGetSymbolAddress((void**)&pbqkv, g_bqkv);

    cudaFuncSetAttribute(gemm_hf<0>, cudaFuncAttributeMaxDynamicSharedMemorySize, GSMEM_BYTES);
    cudaFuncSetAttribute(gemm_hf<1>, cudaFuncAttributeMaxDynamicSharedMemorySize, GSMEM_BYTES);
    cudaFuncSetAttribute(attn_mma, cudaFuncAttributeMaxDynamicSharedMemorySize, ATT_SMEM_BYTES);

    // ---- weight/bias packing (once per call) ----
    const int EE = EMB*EMB;          // 262144
    const int FE = FFD*EMB;          // 1048576
    conv_w4<<<(NLAYER*EE/4 + 255)/256, 256>>>(Wq, pwqkv, EE, 3*EE, 0);
    conv_w4<<<(NLAYER*EE/4 + 255)/256, 256>>>(Wk, pwqkv, EE, 3*EE, EE);
    conv_w4<<<(NLAYER*EE/4 + 255)/256, 256>>>(Wv, pwqkv, EE, 3*EE, 2*EE);
    conv_w4<<<(NLAYER*EE/4 + 255)/256, 256>>>(Wo, pwo, EE, EE, 0);
    conv_w4<<<(NLAYER*FE/4 + 255)/256, 256>>>(W1, pw1, FE, FE, 0);
    conv_w4<<<(NLAYER*FE/4 + 255)/256, 256>>>(W2, pw2, FE, FE, 0);
    pack_bqkv<<<(NLAYER*3*EMB + 255)/256, 256>>>(bq, bk, bv, pbqkv);

    pe_kernel<<<(PSEQ*EMB + 255)/256, 256>>>(ppe);
    embed_kernel<<<(NTOK*EMB + 255)/256, 256>>>(data, conv_w, conv_b, lin_w, lin_b,
                                                ppe, pxh);

    for (int l = 0; l < NLAYER; l++) {
        gemm_hf<0><<<dim3(12,128), 256, GSMEM_BYTES>>>(
            pxh, pwqkv + (size_t)l*3*EE,
            pbqkv + l*3*EMB, pqkv, NTOK, 3*EMB, EMB);

        attn_mma<<<dim3(PSEQ/128, NHEAD, BATCH), 256, ATT_SMEM_BYTES>>>(pqkv, pah);

        gemm_hf<0><<<dim3(4,128), 256, GSMEM_BYTES>>>(
            pah, pwo + (size_t)l*EE,
            bo + l*EMB, pth, NTOK, EMB, EMB);
        add_ln_kernel<<<NTOK, 128>>>(pxh, pth, ln1_g + l*EMB, ln1_b + l*EMB);

        gemm_hf<1><<<dim3(16,128), 256, GSMEM_BYTES>>>(
            pxh, pw1 + (size_t)l*FE,
            b1 + l*FFD, phh, NTOK, FFD, EMB);

        gemm_hf<0><<<dim3(4,128), 256, GSMEM_BYTES>>>(
            phh, pw2 + (size_t)l*FE,
            b2 + l*EMB, pth, NTOK, EMB, FFD);
        add_ln_kernel<<<NTOK, 128>>>(pxh, pth, ln2_g + l*EMB, ln2_b + l*EMB);
    }

    pool_head_kernel<<<BATCH, 512>>>(pxh, Wc, bc, out);
}